// round 2
// baseline (speedup 1.0000x reference)
#include <cuda_runtime.h>
#include <math.h>

#define BB   4
#define SS   1024
#define HIDC 768
#define HH   6
#define DD   64
#define AHC  384
#define KSC  9
#define PADC 4
#define OW   768   // output width = 2*AH

// ---------------- scratch (device globals: no allocations allowed) ----------------
__device__ float g_mq [BB*SS*AHC];
__device__ float g_mk [BB*SS*AHC];
__device__ float g_mv [BB*SS*AHC];
__device__ float g_co [BB*SS*AHC];
__device__ float g_mkc[BB*SS*AHC];
__device__ float g_dwt[BB*SS*HIDC];
__device__ float g_ck [BB*SS*HH*KSC];
__device__ float g_tdsm[BB*SS];

// ---------------- generic fp32 GEMM: C[M,N] = A[M,K] @ B (+bias) ----------------
// BT=false: B is [K,N] row-major. BT=true: B is [N,K] row-major (we use B^T).
template<bool BT, bool BIAS>
__global__ void __launch_bounds__(256) gemm64(const float* __restrict__ A,
                                              const float* __restrict__ Bm,
                                              const float* __restrict__ bias,
                                              float* __restrict__ C,
                                              int M, int N, int K)
{
    __shared__ float As[16][64];
    __shared__ float Bs[16][64];
    const int tid = threadIdx.x;
    const int tx = tid & 15, ty = tid >> 4;
    const int m0 = blockIdx.x * 64, n0 = blockIdx.y * 64;
    const int lr = tid >> 2;          // 0..63
    const int lk = (tid & 3) * 4;     // 0,4,8,12

    float acc[4][4];
#pragma unroll
    for (int i = 0; i < 4; i++)
#pragma unroll
        for (int j = 0; j < 4; j++) acc[i][j] = 0.f;

    for (int k0 = 0; k0 < K; k0 += 16) {
        float4 av = *(const float4*)(A + (size_t)(m0 + lr) * K + k0 + lk);
        As[lk + 0][lr] = av.x; As[lk + 1][lr] = av.y;
        As[lk + 2][lr] = av.z; As[lk + 3][lr] = av.w;
        if (!BT) {
            int bk = tid >> 4, bn = (tid & 15) * 4;
            float4 bv = *(const float4*)(Bm + (size_t)(k0 + bk) * N + n0 + bn);
            Bs[bk][bn + 0] = bv.x; Bs[bk][bn + 1] = bv.y;
            Bs[bk][bn + 2] = bv.z; Bs[bk][bn + 3] = bv.w;
        } else {
            float4 bv = *(const float4*)(Bm + (size_t)(n0 + lr) * K + k0 + lk);
            Bs[lk + 0][lr] = bv.x; Bs[lk + 1][lr] = bv.y;
            Bs[lk + 2][lr] = bv.z; Bs[lk + 3][lr] = bv.w;
        }
        __syncthreads();
#pragma unroll
        for (int k = 0; k < 16; k++) {
            float a[4], bq[4];
#pragma unroll
            for (int i = 0; i < 4; i++) a[i] = As[k][ty * 4 + i];
#pragma unroll
            for (int j = 0; j < 4; j++) bq[j] = Bs[k][tx * 4 + j];
#pragma unroll
            for (int i = 0; i < 4; i++)
#pragma unroll
                for (int j = 0; j < 4; j++) acc[i][j] += a[i] * bq[j];
        }
        __syncthreads();
    }
#pragma unroll
    for (int i = 0; i < 4; i++) {
        int m = m0 + ty * 4 + i;
#pragma unroll
        for (int j = 0; j < 4; j++) {
            int n = n0 + tx * 4 + j;
            float v = acc[i][j];
            if (BIAS) v += bias[n];
            C[(size_t)m * N + n] = v;
        }
    }
}

// ---------------- depthwise conv over sequence (kernel 9, pad 4) ----------------
__global__ void __launch_bounds__(256) dw_kernel(const float* __restrict__ Kin,
                                                 const float* __restrict__ dw_w)
{
    int bs = blockIdx.x;              // b*S + s
    int b = bs >> 10, s = bs & 1023;
    for (int c = threadIdx.x; c < HIDC; c += 256) {
        float acc = 0.f;
#pragma unroll
        for (int k = 0; k < KSC; k++) {
            int sr = s + k - PADC;
            if (sr >= 0 && sr < SS)
                acc += Kin[(size_t)(b * SS + sr) * HIDC + c] * dw_w[c * KSC + k];
        }
        g_dwt[(size_t)bs * HIDC + c] = acc;
    }
}

// ---------------- ck = softmax_K( (mkc*mq) @ ck_W + ck_b ) ----------------
__global__ void __launch_bounds__(64) ck_kernel(const float* __restrict__ ckW,
                                                const float* __restrict__ ckb)
{
    __shared__ float ca[AHC];
    __shared__ float lg[HH * KSC];
    int bs = blockIdx.x, tid = threadIdx.x;
    for (int a = tid; a < AHC; a += 64)
        ca[a] = g_mkc[(size_t)bs * AHC + a] * g_mq[(size_t)bs * AHC + a];
    __syncthreads();
    if (tid < HH * KSC) {
        float acc = ckb[tid];
        for (int a = 0; a < AHC; a++) acc += ca[a] * ckW[a * (HH * KSC) + tid];
        lg[tid] = acc;
    }
    __syncthreads();
    if (tid < HH) {
        float m = -3e38f;
#pragma unroll
        for (int k = 0; k < KSC; k++) m = fmaxf(m, lg[tid * KSC + k]);
        float e[KSC]; float sum = 0.f;
#pragma unroll
        for (int k = 0; k < KSC; k++) { e[k] = expf(lg[tid * KSC + k] - m); sum += e[k]; }
        float invs = 1.f / sum;
#pragma unroll
        for (int k = 0; k < KSC; k++)
            g_ck[(size_t)bs * HH * KSC + tid * KSC + k] = e[k] * invs;
    }
}

// ---------------- conv_out: sliding-window gather of co weighted by ck ----------------
__global__ void __launch_bounds__(128) conv_out_kernel(float* __restrict__ out)
{
    int bs = blockIdx.x;
    int b = bs >> 10, s = bs & 1023;
    __shared__ float cks[HH * KSC];
    if (threadIdx.x < HH * KSC) cks[threadIdx.x] = g_ck[(size_t)bs * HH * KSC + threadIdx.x];
    __syncthreads();
    for (int a = threadIdx.x; a < AHC; a += 128) {
        int h = a >> 6;
        float acc = 0.f;
#pragma unroll
        for (int k = 0; k < KSC; k++) {
            int sr = s + k - PADC;
            if (sr >= 0 && sr < SS)
                acc += g_co[(size_t)(b * SS + sr) * AHC + a] * cks[h * KSC + k];
        }
        out[(size_t)bs * OW + AHC + a] = acc;
    }
}

// ---------------- td softmax (independent of head and query row) ----------------
__global__ void __launch_bounds__(256) tdsm_kernel(const float* __restrict__ td,
                                                   const int* __restrict__ mask)
{
    __shared__ float red[8];
    __shared__ float bc;
    int b = blockIdx.x, tid = threadIdx.x;
    int wid = tid >> 5, ln = tid & 31;

    // 1/norm
    float ss = 0.f;
    for (int j = tid; j < SS; j += 256) { float v = td[b * SS + j]; ss += v * v; }
#pragma unroll
    for (int o = 16; o; o >>= 1) ss += __shfl_xor_sync(0xffffffffu, ss, o);
    if (ln == 0) red[wid] = ss;
    __syncthreads();
    if (tid == 0) {
        float t = 0.f;
        for (int k = 0; k < 8; k++) t += red[k];
        bc = 1.f / fmaxf(sqrtf(t), 1e-12f);
    }
    __syncthreads();
    float inv = bc;

    // masked max of tdn (include -1e4 floor like ref)
    float m = -1e4f;
    for (int j = tid; j < SS; j += 256)
        if (mask[b * SS + j]) m = fmaxf(m, td[b * SS + j] * inv);
#pragma unroll
    for (int o = 16; o; o >>= 1) m = fmaxf(m, __shfl_xor_sync(0xffffffffu, m, o));
    if (ln == 0) red[wid] = m;
    __syncthreads();
    if (tid == 0) {
        float t = -1e4f;
        for (int k = 0; k < 8; k++) t = fmaxf(t, red[k]);
        bc = t;
    }
    __syncthreads();
    float mm = bc;
    __syncthreads();

    // denominator
    float den = 0.f;
    for (int j = tid; j < SS; j += 256)
        if (mask[b * SS + j]) den += expf(td[b * SS + j] * inv - mm);
#pragma unroll
    for (int o = 16; o; o >>= 1) den += __shfl_xor_sync(0xffffffffu, den, o);
    if (ln == 0) red[wid] = den;
    __syncthreads();
    if (tid == 0) {
        float t = 0.f;
        for (int k = 0; k < 8; k++) t += red[k];
        bc = 1.f / t;
    }
    __syncthreads();
    float invden = bc;

    for (int j = tid; j < SS; j += 256) {
        float v = mask[b * SS + j] ? expf(td[b * SS + j] * inv - mm) * invden : 0.f;
        g_tdsm[b * SS + j] = v;
    }
}

// ---------------- attention with distance decay ----------------
// grid (S/8, H, B); 8 warps, one query row per warp. K/V staged in 128x64 smem
// tiles (65-float row pitch, conflict-free). Score rows stored with swizzle
// SIDX(j) = j + (j>>5): both lane-contiguous (cumsum) and lane-strided
// (reductions / scores) accesses land on distinct banks.
__global__ void __launch_bounds__(256) attn_kernel(const int* __restrict__ mask,
                                                   const float* __restrict__ gammas,
                                                   float* __restrict__ out)
{
    extern __shared__ float sm[];
    float* kt  = sm;                       // 128*65
    float* sc  = kt + 128 * 65;            // 8*1056
    float* qs  = sc + 8 * 1056;            // 8*64
    float* msk = qs + 8 * 64;              // 1024
    float* tds = msk + 1024;               // 1024

    const int tid  = threadIdx.x;
    const int w    = tid >> 5, lane = tid & 31;
    const int i0   = blockIdx.x * 8;
    const int h    = blockIdx.y;
    const int b    = blockIdx.z;
    const int i    = i0 + w;

    for (int j = tid; j < SS; j += 256) {
        msk[j] = mask[b * SS + j] ? 1.f : 0.f;
        tds[j] = g_tdsm[b * SS + j];
    }
    for (int idx = tid; idx < 8 * DD; idx += 256) {
        int r = idx >> 6, d = idx & 63;
        qs[r * DD + d] = g_mq[(size_t)(b * SS + i0 + r) * AHC + h * DD + d];
    }
    float gv = gammas[h];
    float gamma = -(gv > 20.f ? gv : log1pf(expf(gv)));   // -softplus

    float* srow = sc + w * 1056;

    // ---- scores = q·k / 8 ----
    for (int jt = 0; jt < 8; jt++) {
        __syncthreads();
        for (int idx = tid; idx < 2048; idx += 256) {
            int r = idx >> 4;
            int d4 = (idx & 15) * 4;
            float4 v = *(const float4*)(g_mk + (size_t)(b * SS + jt * 128 + r) * AHC + h * DD + d4);
            kt[r * 65 + d4 + 0] = v.x; kt[r * 65 + d4 + 1] = v.y;
            kt[r * 65 + d4 + 2] = v.z; kt[r * 65 + d4 + 3] = v.w;
        }
        __syncthreads();
        float a0 = 0.f, a1 = 0.f, a2 = 0.f, a3 = 0.f;
#pragma unroll
        for (int d = 0; d < DD; d++) {
            float qd = qs[w * DD + d];
            a0 += qd * kt[(lane      ) * 65 + d];
            a1 += qd * kt[(lane +  32) * 65 + d];
            a2 += qd * kt[(lane +  64) * 65 + d];
            a3 += qd * kt[(lane +  96) * 65 + d];
        }
        int j;
        j = jt * 128 + lane;       srow[j + (j >> 5)] = a0 * 0.125f;
        j = jt * 128 + lane + 32;  srow[j + (j >> 5)] = a1 * 0.125f;
        j = jt * 128 + lane + 64;  srow[j + (j >> 5)] = a2 * 0.125f;
        j = jt * 128 + lane + 96;  srow[j + (j >> 5)] = a3 * 0.125f;
    }
    __syncwarp();

    // ---- pass 1: masked max (lane-strided: srow[c*33+lane]) ----
    float m1 = -3e38f;
#pragma unroll
    for (int c = 0; c < 32; c++) {
        int j = c * 32 + lane;
        if (msk[j] != 0.f) m1 = fmaxf(m1, srow[c * 33 + lane]);
    }
#pragma unroll
    for (int o = 16; o; o >>= 1) m1 = fmaxf(m1, __shfl_xor_sync(0xffffffffu, m1, o));

    // ---- pass 2: p ~ exp * mask, inclusive cumsum (lane-contiguous chunk) ----
    float cuml[32];
    float run = 0.f;
#pragma unroll
    for (int c = 0; c < 32; c++) {
        int j = lane * 32 + c;
        float p = (msk[j] != 0.f) ? expf(srow[lane * 33 + c] - m1) : 0.f;
        run += p;
        cuml[c] = run;
    }
    float v = run;
#pragma unroll
    for (int o = 1; o < 32; o <<= 1) {
        float t = __shfl_up_sync(0xffffffffu, v, o);
        if (lane >= o) v += t;
    }
    float total = __shfl_sync(0xffffffffu, v, 31);
    float off = v - run;   // exclusive prefix of lane sums
    // normalization: reference uses p = softmax (sums to 1); scale cum by 1/total
    float invtot = 1.f / fmaxf(total, 1e-30f);

    // ---- pass 3: total_effect, modified scores, max ----
    float m2 = -3e38f;
#pragma unroll
    for (int c = 0; c < 32; c++) {
        int j = lane * 32 + c;
        float s2;
        if (msk[j] != 0.f) {
            float cum = cuml[c] + off;
            float pos = fabsf((float)(j - i));
            float rem = (total - cum) * invtot;            // disttotal - distcum (normalized)
            float ds = sqrtf(fmaxf(rem * pos, 0.f));
            float te = expf(gamma * ds);
            te = fminf(fmaxf(te, 1e-5f), 1e5f);
            if (j < i) te -= tds[j];
            s2 = srow[lane * 33 + c] * te;
        } else {
            s2 = -1e8f;
        }
        srow[lane * 33 + c] = s2;
        m2 = fmaxf(m2, s2);
    }
#pragma unroll
    for (int o = 16; o; o >>= 1) m2 = fmaxf(m2, __shfl_xor_sync(0xffffffffu, m2, o));

    // ---- pass 4: exp + sum (normalize at the end, it is linear) ----
    float sum2 = 0.f;
#pragma unroll
    for (int c = 0; c < 32; c++) {
        float e = expf(srow[lane * 33 + c] - m2);
        srow[lane * 33 + c] = e;
        sum2 += e;
    }
#pragma unroll
    for (int o = 16; o; o >>= 1) sum2 += __shfl_xor_sync(0xffffffffu, sum2, o);
    float invs = 1.f / sum2;

    // ---- PV ----
    float acc0 = 0.f, acc1 = 0.f;
    for (int jt = 0; jt < 8; jt++) {
        __syncthreads();
        for (int idx = tid; idx < 2048; idx += 256) {
            int r = idx >> 4;
            int d4 = (idx & 15) * 4;
            float4 vv = *(const float4*)(g_mv + (size_t)(b * SS + jt * 128 + r) * AHC + h * DD + d4);
            kt[r * 65 + d4 + 0] = vv.x; kt[r * 65 + d4 + 1] = vv.y;
            kt[r * 65 + d4 + 2] = vv.z; kt[r * 65 + d4 + 3] = vv.w;
        }
        __syncthreads();
        int jb = jt * 128;
#pragma unroll 8
        for (int jl = 0; jl < 128; jl++) {
            int j = jb + jl;
            float pr = srow[j + (j >> 5)];
            acc0 += pr * kt[jl * 65 + lane];
            acc1 += pr * kt[jl * 65 + lane + 32];
        }
    }
    size_t ob = (size_t)(b * SS + i) * OW + h * DD;
    out[ob + lane]      = acc0 * invs;
    out[ob + lane + 32] = acc1 * invs;
}

// ---------------- launch ----------------
extern "C" void kernel_launch(void* const* d_in, const int* in_sizes, int n_in,
                              void* d_out, int out_size)
{
    const float* Q      = (const float*)d_in[0];
    const float* Kin    = (const float*)d_in[1];
    const float* V      = (const float*)d_in[2];
    const float* td     = (const float*)d_in[3];
    const int*   mask   = (const int*)  d_in[4];
    const float* Wq     = (const float*)d_in[5];
    const float* Wk     = (const float*)d_in[6];
    const float* Wv     = (const float*)d_in[7];
    const float* dw_w   = (const float*)d_in[8];
    const float* pw_w   = (const float*)d_in[9];
    const float* sep_b  = (const float*)d_in[10];
    const float* ck_W   = (const float*)d_in[11];
    const float* ck_b   = (const float*)d_in[12];
    const float* co_W   = (const float*)d_in[13];
    const float* co_b   = (const float*)d_in[14];
    const float* gammas = (const float*)d_in[15];
    float* out = (float*)d_out;

    float *p_mq, *p_mk, *p_mv, *p_co, *p_mkc, *p_dwt;
    cudaGetSymbolAddress((void**)&p_mq,  g_mq);
    cudaGetSymbolAddress((void**)&p_mk,  g_mk);
    cudaGetSymbolAddress((void**)&p_mv,  g_mv);
    cudaGetSymbolAddress((void**)&p_co,  g_co);
    cudaGetSymbolAddress((void**)&p_mkc, g_mkc);
    cudaGetSymbolAddress((void**)&p_dwt, g_dwt);

    const int M = BB * SS;
    dim3 gg(M / 64, AHC / 64);

    gemm64<false, false><<<gg, 256>>>(Q,   Wq,   nullptr, p_mq,  M, AHC, HIDC);
    gemm64<false, false><<<gg, 256>>>(Kin, Wk,   nullptr, p_mk,  M, AHC, HIDC);
    gemm64<false, false><<<gg, 256>>>(V,   Wv,   nullptr, p_mv,  M, AHC, HIDC);
    gemm64<false, true ><<<gg, 256>>>(V,   co_W, co_b,    p_co,  M, AHC, HIDC);

    dw_kernel<<<BB * SS, 256>>>(Kin, dw_w);
    gemm64<true, true><<<gg, 256>>>(p_dwt, pw_w, sep_b, p_mkc, M, AHC, HIDC);

    ck_kernel<<<BB * SS, 64>>>(ck_W, ck_b);
    conv_out_kernel<<<BB * SS, 128>>>(out);

    tdsm_kernel<<<BB, 256>>>(td, mask);

    int smem = (128 * 65 + 8 * 1056 + 8 * 64 + 1024 + 1024) * (int)sizeof(float);
    cudaFuncSetAttribute(attn_kernel, cudaFuncAttributeMaxDynamicSharedMemorySize, smem);
    attn_kernel<<<dim3(SS / 8, HH, BB), 256, smem>>>(mask, gammas, out);
}

// round 3
// speedup vs baseline: 1.0403x; 1.0403x over previous
#include <cuda_runtime.h>
#include <math.h>

#define BB   4
#define SS   1024
#define HIDC 768
#define HH   6
#define DD   64
#define AHC  384
#define KSC  9
#define PADC 4
#define OW   768   // output width = 2*AH
#define CKN  54    // H*KS

typedef unsigned long long ull;

// ---------------- f32x2 packed helpers ----------------
__device__ __forceinline__ void ffma2(ull& d, ull a, ull b) {
    asm("fma.rn.f32x2 %0, %1, %2, %3;" : "=l"(d) : "l"(a), "l"(b), "l"(d));
}
__device__ __forceinline__ ull pack2(float lo, float hi) {
    ull r; asm("mov.b64 %0, {%1, %2};" : "=l"(r) : "f"(lo), "f"(hi)); return r;
}
__device__ __forceinline__ void unpack2(float& lo, float& hi, ull v) {
    asm("mov.b64 {%0, %1}, %2;" : "=f"(lo), "=f"(hi) : "l"(v));
}

// ---------------- scratch (device globals: no allocations allowed) ----------------
__device__ float g_mq [BB*SS*AHC];
__device__ float g_mk [BB*SS*AHC];
__device__ float g_mv [BB*SS*AHC];
__device__ float g_co [BB*SS*AHC];
__device__ float g_mkc[BB*SS*AHC];
__device__ float g_dwt[BB*SS*HIDC];
__device__ float g_ck [BB*SS*CKN];
__device__ float g_tdsm[BB*SS];

// ---------------- GEMM core: C[M,N] = A[M,K] @ B (+bias), 128x64 tile, f32x2 ----------------
// BT=false: B is [K,N] row-major. BT=true: B is [N,K] row-major (C = A @ B^T).
// NGUARD: N not multiple of 64 (guarded B loads / C stores). AMUL: A := A .* A2.
template<bool BT, bool BIAS, bool NGUARD, bool AMUL>
__device__ __forceinline__ void gemm_core(const float* __restrict__ A,
                                          const float* __restrict__ A2,
                                          const float* __restrict__ Bm,
                                          const float* __restrict__ bias,
                                          float* __restrict__ C,
                                          int N, int K, int m0, int n0)
{
    __shared__ float As[16][128];
    __shared__ float Bs[16][64];
    const int tid = threadIdx.x;
    const int ty = tid >> 4, tx = tid & 15;     // 16 m-groups x 16 n-groups
    const int lr = tid >> 1, lk = (tid & 1) * 8;

    ull acc[8][2];
#pragma unroll
    for (int i = 0; i < 8; i++) { acc[i][0] = 0ull; acc[i][1] = 0ull; }

    for (int k0 = 0; k0 < K; k0 += 16) {
        // ---- stage A (128 x 16) ----
        {
            const float* ap = A + (size_t)(m0 + lr) * K + k0 + lk;
            float4 a0 = *(const float4*)(ap);
            float4 a1 = *(const float4*)(ap + 4);
            if (AMUL) {
                const float* a2p = A2 + (size_t)(m0 + lr) * K + k0 + lk;
                float4 m0v = *(const float4*)(a2p);
                float4 m1v = *(const float4*)(a2p + 4);
                a0.x *= m0v.x; a0.y *= m0v.y; a0.z *= m0v.z; a0.w *= m0v.w;
                a1.x *= m1v.x; a1.y *= m1v.y; a1.z *= m1v.z; a1.w *= m1v.w;
            }
            As[lk + 0][lr] = a0.x; As[lk + 1][lr] = a0.y;
            As[lk + 2][lr] = a0.z; As[lk + 3][lr] = a0.w;
            As[lk + 4][lr] = a1.x; As[lk + 5][lr] = a1.y;
            As[lk + 6][lr] = a1.z; As[lk + 7][lr] = a1.w;
        }
        // ---- stage B (16 x 64) ----
        if (!BT) {
            int bk = tid >> 4, bn = (tid & 15) * 4;
            if (!NGUARD) {
                float4 bv = *(const float4*)(Bm + (size_t)(k0 + bk) * N + n0 + bn);
                Bs[bk][bn + 0] = bv.x; Bs[bk][bn + 1] = bv.y;
                Bs[bk][bn + 2] = bv.z; Bs[bk][bn + 3] = bv.w;
            } else {
#pragma unroll
                for (int j = 0; j < 4; j++) {
                    int n = n0 + bn + j;
                    Bs[bk][bn + j] = (n < N) ? Bm[(size_t)(k0 + bk) * N + n] : 0.f;
                }
            }
        } else {
            int bn = tid >> 2, bkk = (tid & 3) * 4;
            float4 bv = *(const float4*)(Bm + (size_t)(n0 + bn) * K + k0 + bkk);
            Bs[bkk + 0][bn] = bv.x; Bs[bkk + 1][bn] = bv.y;
            Bs[bkk + 2][bn] = bv.z; Bs[bkk + 3][bn] = bv.w;
        }
        __syncthreads();
#pragma unroll
        for (int k = 0; k < 16; k++) {
            float4 aA = *(const float4*)&As[k][ty * 8];
            float4 aB = *(const float4*)&As[k][ty * 8 + 4];
            ull b01 = *(const ull*)&Bs[k][tx * 4];
            ull b23 = *(const ull*)&Bs[k][tx * 4 + 2];
            ull ap;
            ap = pack2(aA.x, aA.x); ffma2(acc[0][0], ap, b01); ffma2(acc[0][1], ap, b23);
            ap = pack2(aA.y, aA.y); ffma2(acc[1][0], ap, b01); ffma2(acc[1][1], ap, b23);
            ap = pack2(aA.z, aA.z); ffma2(acc[2][0], ap, b01); ffma2(acc[2][1], ap, b23);
            ap = pack2(aA.w, aA.w); ffma2(acc[3][0], ap, b01); ffma2(acc[3][1], ap, b23);
            ap = pack2(aB.x, aB.x); ffma2(acc[4][0], ap, b01); ffma2(acc[4][1], ap, b23);
            ap = pack2(aB.y, aB.y); ffma2(acc[5][0], ap, b01); ffma2(acc[5][1], ap, b23);
            ap = pack2(aB.z, aB.z); ffma2(acc[6][0], ap, b01); ffma2(acc[6][1], ap, b23);
            ap = pack2(aB.w, aB.w); ffma2(acc[7][0], ap, b01); ffma2(acc[7][1], ap, b23);
        }
        __syncthreads();
    }
#pragma unroll
    for (int i = 0; i < 8; i++) {
        int m = m0 + ty * 8 + i;
#pragma unroll
        for (int p = 0; p < 2; p++) {
            float lo, hi; unpack2(lo, hi, acc[i][p]);
            int n = n0 + tx * 4 + 2 * p;
            if (!NGUARD || n < N) {
                float v = lo; if (BIAS) v += bias[n];
                C[(size_t)m * N + n] = v;
            }
            if (!NGUARD || n + 1 < N) {
                float v = hi; if (BIAS) v += bias[n + 1];
                C[(size_t)m * N + n + 1] = v;
            }
        }
    }
}

// fused 4-way projection GEMM: z selects (A, B, bias, C)
__global__ void __launch_bounds__(256) gemm_fused(const float* __restrict__ Q,
                                                  const float* __restrict__ Kin,
                                                  const float* __restrict__ V,
                                                  const float* __restrict__ Wq,
                                                  const float* __restrict__ Wk,
                                                  const float* __restrict__ Wv,
                                                  const float* __restrict__ coW,
                                                  const float* __restrict__ cob,
                                                  float* __restrict__ mq,
                                                  float* __restrict__ mk,
                                                  float* __restrict__ mv,
                                                  float* __restrict__ co)
{
    int m0 = blockIdx.x * 128, n0 = blockIdx.y * 64;
    switch (blockIdx.z) {
    case 0: gemm_core<false,false,false,false>(Q,   nullptr, Wq,  nullptr, mq, AHC, HIDC, m0, n0); break;
    case 1: gemm_core<false,false,false,false>(Kin, nullptr, Wk,  nullptr, mk, AHC, HIDC, m0, n0); break;
    case 2: gemm_core<false,false,false,false>(V,   nullptr, Wv,  nullptr, mv, AHC, HIDC, m0, n0); break;
    default:gemm_core<false,true, false,false>(V,   nullptr, coW, cob,     co, AHC, HIDC, m0, n0); break;
    }
}

// pointwise conv GEMM: mkc = dwt @ pw_w^T + sep_b
__global__ void __launch_bounds__(256) gemm_pw(const float* __restrict__ dwt,
                                               const float* __restrict__ pw,
                                               const float* __restrict__ sb,
                                               float* __restrict__ mkc)
{
    gemm_core<true, true, false, false>(dwt, nullptr, pw, sb, mkc,
                                        AHC, HIDC, blockIdx.x * 128, blockIdx.y * 64);
}

// ck logits GEMM: L = (mkc .* mq) @ ck_W + ck_b   (N=54, guarded)
__global__ void __launch_bounds__(256) gemm_ck(const float* __restrict__ mkc,
                                               const float* __restrict__ mq,
                                               const float* __restrict__ ckW,
                                               const float* __restrict__ ckb,
                                               float* __restrict__ lg)
{
    gemm_core<false, true, true, true>(mkc, mq, ckW, ckb, lg,
                                       CKN, AHC, blockIdx.x * 128, 0);
}

// ck softmax over KS=9, in place on g_ck
__global__ void __launch_bounds__(256) cksm_kernel()
{
    int row = blockIdx.x * 256 + threadIdx.x;     // (b*S*H + h) flattened: BB*SS*HH rows
    if (row >= BB * SS * HH) return;
    float* p = g_ck + (size_t)row * KSC;
    float v[KSC];
    float m = -3e38f;
#pragma unroll
    for (int k = 0; k < KSC; k++) { v[k] = p[k]; m = fmaxf(m, v[k]); }
    float sum = 0.f;
#pragma unroll
    for (int k = 0; k < KSC; k++) { v[k] = expf(v[k] - m); sum += v[k]; }
    float invs = 1.f / sum;
#pragma unroll
    for (int k = 0; k < KSC; k++) p[k] = v[k] * invs;
}

// ---------------- depthwise conv over sequence (kernel 9, pad 4) ----------------
__global__ void __launch_bounds__(256) dw_kernel(const float* __restrict__ Kin,
                                                 const float* __restrict__ dw_w)
{
    int bs = blockIdx.x;              // b*S + s
    int b = bs >> 10, s = bs & 1023;
    for (int c = threadIdx.x; c < HIDC; c += 256) {
        float acc = 0.f;
#pragma unroll
        for (int k = 0; k < KSC; k++) {
            int sr = s + k - PADC;
            if (sr >= 0 && sr < SS)
                acc += Kin[(size_t)(b * SS + sr) * HIDC + c] * dw_w[c * KSC + k];
        }
        g_dwt[(size_t)bs * HIDC + c] = acc;
    }
}

// ---------------- conv_out: sliding-window gather of co weighted by ck ----------------
__global__ void __launch_bounds__(128) conv_out_kernel(float* __restrict__ out)
{
    int bs = blockIdx.x;
    int b = bs >> 10, s = bs & 1023;
    __shared__ float cks[CKN];
    if (threadIdx.x < CKN) cks[threadIdx.x] = g_ck[(size_t)bs * CKN + threadIdx.x];
    __syncthreads();
    for (int a = threadIdx.x; a < AHC; a += 128) {
        int h = a >> 6;
        float acc = 0.f;
#pragma unroll
        for (int k = 0; k < KSC; k++) {
            int sr = s + k - PADC;
            if (sr >= 0 && sr < SS)
                acc += g_co[(size_t)(b * SS + sr) * AHC + a] * cks[h * KSC + k];
        }
        out[(size_t)bs * OW + AHC + a] = acc;
    }
}

// ---------------- td softmax (independent of head and query row) ----------------
__global__ void __launch_bounds__(256) tdsm_kernel(const float* __restrict__ td,
                                                   const int* __restrict__ mask)
{
    __shared__ float red[8];
    __shared__ float bc;
    int b = blockIdx.x, tid = threadIdx.x;
    int wid = tid >> 5, ln = tid & 31;

    float ss = 0.f;
    for (int j = tid; j < SS; j += 256) { float v = td[b * SS + j]; ss += v * v; }
#pragma unroll
    for (int o = 16; o; o >>= 1) ss += __shfl_xor_sync(0xffffffffu, ss, o);
    if (ln == 0) red[wid] = ss;
    __syncthreads();
    if (tid == 0) {
        float t = 0.f;
        for (int k = 0; k < 8; k++) t += red[k];
        bc = 1.f / fmaxf(sqrtf(t), 1e-12f);
    }
    __syncthreads();
    float inv = bc;

    float m = -1e4f;
    for (int j = tid; j < SS; j += 256)
        if (mask[b * SS + j]) m = fmaxf(m, td[b * SS + j] * inv);
#pragma unroll
    for (int o = 16; o; o >>= 1) m = fmaxf(m, __shfl_xor_sync(0xffffffffu, m, o));
    if (ln == 0) red[wid] = m;
    __syncthreads();
    if (tid == 0) {
        float t = -1e4f;
        for (int k = 0; k < 8; k++) t = fmaxf(t, red[k]);
        bc = t;
    }
    __syncthreads();
    float mm = bc;
    __syncthreads();

    float den = 0.f;
    for (int j = tid; j < SS; j += 256)
        if (mask[b * SS + j]) den += expf(td[b * SS + j] * inv - mm);
#pragma unroll
    for (int o = 16; o; o >>= 1) den += __shfl_xor_sync(0xffffffffu, den, o);
    if (ln == 0) red[wid] = den;
    __syncthreads();
    if (tid == 0) {
        float t = 0.f;
        for (int k = 0; k < 8; k++) t += red[k];
        bc = 1.f / t;
    }
    __syncthreads();
    float invden = bc;

    for (int j = tid; j < SS; j += 256) {
        float v = mask[b * SS + j] ? expf(td[b * SS + j] * inv - mm) * invden : 0.f;
        g_tdsm[b * SS + j] = v;
    }
}

// ---------------- attention with distance decay (f32x2 packed) ----------------
// grid (S/8, H, B); 8 warps, one query row per warp. K/V staged in 128x66 smem
// (8B-aligned rows, conflict-free .64 access both ways). Score rows swizzled
// SIDX(j) = j + (j>>5) as before.
__global__ void __launch_bounds__(256) attn_kernel(const int* __restrict__ mask,
                                                   const float* __restrict__ gammas,
                                                   float* __restrict__ out)
{
    extern __shared__ float sm[];
    float* kt  = sm;                       // 128*66
    float* sc  = kt + 128 * 66;            // 8*1056
    float* qs  = sc + 8 * 1056;            // 8*64
    float* msk = qs + 8 * 64;              // 1024
    float* tds = msk + 1024;               // 1024

    const int tid  = threadIdx.x;
    const int w    = tid >> 5, lane = tid & 31;
    const int i0   = blockIdx.x * 8;
    const int h    = blockIdx.y;
    const int b    = blockIdx.z;
    const int i    = i0 + w;

    for (int j = tid; j < SS; j += 256) {
        msk[j] = mask[b * SS + j] ? 1.f : 0.f;
        tds[j] = g_tdsm[b * SS + j];
    }
    {   // stage q as float2 pairs: 8 rows x 32 pairs = 256 float2
        int r = tid >> 5, dp = tid & 31;
        *(float2*)&qs[r * 64 + 2 * dp] =
            *(const float2*)(g_mq + (size_t)(b * SS + i0 + r) * AHC + h * DD + 2 * dp);
    }
    float gv = gammas[h];
    float gamma = -(gv > 20.f ? gv : log1pf(expf(gv)));   // -softplus

    float* srow = sc + w * 1056;
    const ull* qrow = (const ull*)&qs[w * 64];

    // ---- scores = q·k / 8 ----
    for (int jt = 0; jt < 8; jt++) {
        __syncthreads();
        for (int idx = tid; idx < 4096; idx += 256) {
            int r = idx >> 5, dp = idx & 31;
            *(float2*)&kt[r * 66 + 2 * dp] =
                *(const float2*)(g_mk + (size_t)(b * SS + jt * 128 + r) * AHC + h * DD + 2 * dp);
        }
        __syncthreads();
        ull a0 = 0ull, a1 = 0ull, a2 = 0ull, a3 = 0ull;
#pragma unroll
        for (int dp = 0; dp < 32; dp++) {
            ull q2 = qrow[dp];
            ffma2(a0, q2, *(const ull*)&kt[(lane      ) * 66 + 2 * dp]);
            ffma2(a1, q2, *(const ull*)&kt[(lane +  32) * 66 + 2 * dp]);
            ffma2(a2, q2, *(const ull*)&kt[(lane +  64) * 66 + 2 * dp]);
            ffma2(a3, q2, *(const ull*)&kt[(lane +  96) * 66 + 2 * dp]);
        }
        float lo, hi; int j;
        unpack2(lo, hi, a0); j = jt * 128 + lane;      srow[j + (j >> 5)] = (lo + hi) * 0.125f;
        unpack2(lo, hi, a1); j = jt * 128 + lane + 32; srow[j + (j >> 5)] = (lo + hi) * 0.125f;
        unpack2(lo, hi, a2); j = jt * 128 + lane + 64; srow[j + (j >> 5)] = (lo + hi) * 0.125f;
        unpack2(lo, hi, a3); j = jt * 128 + lane + 96; srow[j + (j >> 5)] = (lo + hi) * 0.125f;
    }
    __syncwarp();

    // ---- pass 1: masked max (lane-strided) ----
    float m1 = -3e38f;
#pragma unroll
    for (int c = 0; c < 32; c++) {
        int j = c * 32 + lane;
        if (msk[j] != 0.f) m1 = fmaxf(m1, srow[c * 33 + lane]);
    }
#pragma unroll
    for (int o = 16; o; o >>= 1) m1 = fmaxf(m1, __shfl_xor_sync(0xffffffffu, m1, o));

    // ---- pass 2: p ~ exp * mask, inclusive cumsum (lane-contiguous chunk) ----
    float cuml[32];
    float run = 0.f;
#pragma unroll
    for (int c = 0; c < 32; c++) {
        int j = lane * 32 + c;
        float p = (msk[j] != 0.f) ? expf(srow[lane * 33 + c] - m1) : 0.f;
        run += p;
        cuml[c] = run;
    }
    float v = run;
#pragma unroll
    for (int o = 1; o < 32; o <<= 1) {
        float t = __shfl_up_sync(0xffffffffu, v, o);
        if (lane >= o) v += t;
    }
    float total = __shfl_sync(0xffffffffu, v, 31);
    float off = v - run;   // exclusive prefix of lane sums
    float invtot = 1.f / fmaxf(total, 1e-30f);

    // ---- pass 3: total_effect, modified scores, max ----
    float m2 = -3e38f;
#pragma unroll
    for (int c = 0; c < 32; c++) {
        int j = lane * 32 + c;
        float s2;
        if (msk[j] != 0.f) {
            float cum = cuml[c] + off;
            float pos = fabsf((float)(j - i));
            float rem = (total - cum) * invtot;
            float ds = sqrtf(fmaxf(rem * pos, 0.f));
            float te = expf(gamma * ds);
            te = fminf(fmaxf(te, 1e-5f), 1e5f);
            if (j < i) te -= tds[j];
            s2 = srow[lane * 33 + c] * te;
        } else {
            s2 = -1e8f;
        }
        srow[lane * 33 + c] = s2;
        m2 = fmaxf(m2, s2);
    }
#pragma unroll
    for (int o = 16; o; o >>= 1) m2 = fmaxf(m2, __shfl_xor_sync(0xffffffffu, m2, o));

    // ---- pass 4: exp + sum ----
    float sum2 = 0.f;
#pragma unroll
    for (int c = 0; c < 32; c++) {
        float e = expf(srow[lane * 33 + c] - m2);
        srow[lane * 33 + c] = e;
        sum2 += e;
    }
#pragma unroll
    for (int o = 16; o; o >>= 1) sum2 += __shfl_xor_sync(0xffffffffu, sum2, o);
    float invs = 1.f / sum2;

    // ---- PV: lane owns d = 2*lane, 2*lane+1 ----
    ull accd = 0ull;
    for (int jt = 0; jt < 8; jt++) {
        __syncthreads();
        for (int idx = tid; idx < 4096; idx += 256) {
            int r = idx >> 5, dp = idx & 31;
            *(float2*)&kt[r * 66 + 2 * dp] =
                *(const float2*)(g_mv + (size_t)(b * SS + jt * 128 + r) * AHC + h * DD + 2 * dp);
        }
        __syncthreads();
        int jb = jt * 128;
#pragma unroll 8
        for (int jl = 0; jl < 128; jl++) {
            int j = jb + jl;
            float pr = srow[j + (j >> 5)];
            ull prp = pack2(pr, pr);
            ffma2(accd, prp, *(const ull*)&kt[jl * 66 + 2 * lane]);
        }
    }
    float lo, hi; unpack2(lo, hi, accd);
    size_t ob = (size_t)(b * SS + i) * OW + h * DD;
    *(float2*)(out + ob + 2 * lane) = make_float2(lo * invs, hi * invs);
}

// ---------------- launch ----------------
extern "C" void kernel_launch(void* const* d_in, const int* in_sizes, int n_in,
                              void* d_out, int out_size)
{
    const float* Q      = (const float*)d_in[0];
    const float* Kin    = (const float*)d_in[1];
    const float* V      = (const float*)d_in[2];
    const float* td     = (const float*)d_in[3];
    const int*   mask   = (const int*)  d_in[4];
    const float* Wq     = (const float*)d_in[5];
    const float* Wk     = (const float*)d_in[6];
    const float* Wv     = (const float*)d_in[7];
    const float* dw_w   = (const float*)d_in[8];
    const float* pw_w   = (const float*)d_in[9];
    const float* sep_b  = (const float*)d_in[10];
    const float* ck_W   = (const float*)d_in[11];
    const float* ck_b   = (const float*)d_in[12];
    const float* co_W   = (const float*)d_in[13];
    const float* co_b   = (const float*)d_in[14];
    const float* gammas = (const float*)d_in[15];
    float* out = (float*)d_out;

    float *p_mq, *p_mk, *p_mv, *p_co, *p_mkc, *p_dwt;
    cudaGetSymbolAddress((void**)&p_mq,  g_mq);
    cudaGetSymbolAddress((void**)&p_mk,  g_mk);
    cudaGetSymbolAddress((void**)&p_mv,  g_mv);
    cudaGetSymbolAddress((void**)&p_co,  g_co);
    cudaGetSymbolAddress((void**)&p_mkc, g_mkc);
    cudaGetSymbolAddress((void**)&p_dwt, g_dwt);
    float* p_ck;
    cudaGetSymbolAddress((void**)&p_ck, g_ck);

    const int M = BB * SS;

    gemm_fused<<<dim3(M / 128, AHC / 64, 4), 256>>>(Q, Kin, V, Wq, Wk, Wv, co_W, co_b,
                                                    p_mq, p_mk, p_mv, p_co);

    dw_kernel<<<BB * SS, 256>>>(Kin, dw_w);
    gemm_pw<<<dim3(M / 128, AHC / 64), 256>>>(p_dwt, pw_w, sep_b, p_mkc);

    gemm_ck<<<dim3(M / 128, 1), 256>>>(p_mkc, p_mq, ck_W, ck_b, p_ck);
    cksm_kernel<<<(BB * SS * HH + 255) / 256, 256>>>();
    conv_out_kernel<<<BB * SS, 128>>>(out);

    tdsm_kernel<<<BB, 256>>>(td, mask);

    int smem = (128 * 66 + 8 * 1056 + 8 * 64 + 1024 + 1024) * (int)sizeof(float);
    cudaFuncSetAttribute(attn_kernel, cudaFuncAttributeMaxDynamicSharedMemorySize, smem);
    attn_kernel<<<dim3(SS / 8, HH, BB), 256, smem>>>(mask, gammas, out);
}

// round 4
// speedup vs baseline: 1.1785x; 1.1328x over previous
#include <cuda_runtime.h>
#include <math.h>

#define BB   4
#define SS   1024
#define HIDC 768
#define HH   6
#define DD   64
#define AHC  384
#define KSC  9
#define PADC 4
#define OW   768   // output width = 2*AH
#define CKN  54    // H*KS
#define TIQ  32    // query rows per attention block
#define RPW  4     // query rows per warp

typedef unsigned long long ull;

// ---------------- f32x2 packed helpers ----------------
__device__ __forceinline__ void ffma2(ull& d, ull a, ull b) {
    asm("fma.rn.f32x2 %0, %1, %2, %3;" : "=l"(d) : "l"(a), "l"(b), "l"(d));
}
__device__ __forceinline__ ull pack2(float lo, float hi) {
    ull r; asm("mov.b64 %0, {%1, %2};" : "=l"(r) : "f"(lo), "f"(hi)); return r;
}
__device__ __forceinline__ void unpack2(float& lo, float& hi, ull v) {
    asm("mov.b64 {%0, %1}, %2;" : "=f"(lo), "=f"(hi) : "l"(v));
}

// ---------------- scratch (device globals: no allocations allowed) ----------------
__device__ float g_mq [BB*SS*AHC];
__device__ float g_mk [BB*SS*AHC];
__device__ float g_mv [BB*SS*AHC];
__device__ float g_co [BB*SS*AHC];
__device__ float g_mkc[BB*SS*AHC];
__device__ float g_dwt[BB*SS*HIDC];
__device__ float g_ck [BB*SS*CKN];
__device__ float g_ckp[3*BB*SS*CKN];   // split-K partials for ck logits
__device__ float g_tdsm[BB*SS];

// ---------------- GEMM core: C[M,N] = A[M,K] @ B (+bias), 128x64 tile, f32x2 ----------------
// BT=false: B is [K,N] row-major. BT=true: B is [N,K] row-major (C = A @ B^T).
// NGUARD: N not multiple of 64 (guarded B loads / C stores). AMUL: A := A .* A2.
// [kBeg,kEnd) selects a K-slice (for split-K).
template<bool BT, bool BIAS, bool NGUARD, bool AMUL>
__device__ __forceinline__ void gemm_core(const float* __restrict__ A,
                                          const float* __restrict__ A2,
                                          const float* __restrict__ Bm,
                                          const float* __restrict__ bias,
                                          float* __restrict__ C,
                                          int N, int K, int m0, int n0,
                                          int kBeg, int kEnd)
{
    __shared__ float As[16][128];
    __shared__ float Bs[16][64];
    const int tid = threadIdx.x;
    const int ty = tid >> 4, tx = tid & 15;     // 16 m-groups x 16 n-groups
    const int lr = tid >> 1, lk = (tid & 1) * 8;

    ull acc[8][2];
#pragma unroll
    for (int i = 0; i < 8; i++) { acc[i][0] = 0ull; acc[i][1] = 0ull; }

    for (int k0 = kBeg; k0 < kEnd; k0 += 16) {
        // ---- stage A (128 x 16) ----
        {
            const float* ap = A + (size_t)(m0 + lr) * K + k0 + lk;
            float4 a0 = *(const float4*)(ap);
            float4 a1 = *(const float4*)(ap + 4);
            if (AMUL) {
                const float* a2p = A2 + (size_t)(m0 + lr) * K + k0 + lk;
                float4 m0v = *(const float4*)(a2p);
                float4 m1v = *(const float4*)(a2p + 4);
                a0.x *= m0v.x; a0.y *= m0v.y; a0.z *= m0v.z; a0.w *= m0v.w;
                a1.x *= m1v.x; a1.y *= m1v.y; a1.z *= m1v.z; a1.w *= m1v.w;
            }
            As[lk + 0][lr] = a0.x; As[lk + 1][lr] = a0.y;
            As[lk + 2][lr] = a0.z; As[lk + 3][lr] = a0.w;
            As[lk + 4][lr] = a1.x; As[lk + 5][lr] = a1.y;
            As[lk + 6][lr] = a1.z; As[lk + 7][lr] = a1.w;
        }
        // ---- stage B (16 x 64) ----
        if (!BT) {
            int bk = tid >> 4, bn = (tid & 15) * 4;
            if (!NGUARD) {
                float4 bv = *(const float4*)(Bm + (size_t)(k0 + bk) * N + n0 + bn);
                Bs[bk][bn + 0] = bv.x; Bs[bk][bn + 1] = bv.y;
                Bs[bk][bn + 2] = bv.z; Bs[bk][bn + 3] = bv.w;
            } else {
#pragma unroll
                for (int j = 0; j < 4; j++) {
                    int n = n0 + bn + j;
                    Bs[bk][bn + j] = (n < N) ? Bm[(size_t)(k0 + bk) * N + n] : 0.f;
                }
            }
        } else {
            int bn = tid >> 2, bkk = (tid & 3) * 4;
            float4 bv = *(const float4*)(Bm + (size_t)(n0 + bn) * K + k0 + bkk);
            Bs[bkk + 0][bn] = bv.x; Bs[bkk + 1][bn] = bv.y;
            Bs[bkk + 2][bn] = bv.z; Bs[bkk + 3][bn] = bv.w;
        }
        __syncthreads();
#pragma unroll
        for (int k = 0; k < 16; k++) {
            float4 aA = *(const float4*)&As[k][ty * 8];
            float4 aB = *(const float4*)&As[k][ty * 8 + 4];
            ull b01 = *(const ull*)&Bs[k][tx * 4];
            ull b23 = *(const ull*)&Bs[k][tx * 4 + 2];
            ull ap;
            ap = pack2(aA.x, aA.x); ffma2(acc[0][0], ap, b01); ffma2(acc[0][1], ap, b23);
            ap = pack2(aA.y, aA.y); ffma2(acc[1][0], ap, b01); ffma2(acc[1][1], ap, b23);
            ap = pack2(aA.z, aA.z); ffma2(acc[2][0], ap, b01); ffma2(acc[2][1], ap, b23);
            ap = pack2(aA.w, aA.w); ffma2(acc[3][0], ap, b01); ffma2(acc[3][1], ap, b23);
            ap = pack2(aB.x, aB.x); ffma2(acc[4][0], ap, b01); ffma2(acc[4][1], ap, b23);
            ap = pack2(aB.y, aB.y); ffma2(acc[5][0], ap, b01); ffma2(acc[5][1], ap, b23);
            ap = pack2(aB.z, aB.z); ffma2(acc[6][0], ap, b01); ffma2(acc[6][1], ap, b23);
            ap = pack2(aB.w, aB.w); ffma2(acc[7][0], ap, b01); ffma2(acc[7][1], ap, b23);
        }
        __syncthreads();
    }
#pragma unroll
    for (int i = 0; i < 8; i++) {
        int m = m0 + ty * 8 + i;
#pragma unroll
        for (int p = 0; p < 2; p++) {
            float lo, hi; unpack2(lo, hi, acc[i][p]);
            int n = n0 + tx * 4 + 2 * p;
            if (!NGUARD || n < N) {
                float v = lo; if (BIAS) v += bias[n];
                C[(size_t)m * N + n] = v;
            }
            if (!NGUARD || n + 1 < N) {
                float v = hi; if (BIAS) v += bias[n + 1];
                C[(size_t)m * N + n + 1] = v;
            }
        }
    }
}

// fused 4-way projection GEMM: z selects (A, B, bias, C)
__global__ void __launch_bounds__(256) gemm_fused(const float* __restrict__ Q,
                                                  const float* __restrict__ Kin,
                                                  const float* __restrict__ V,
                                                  const float* __restrict__ Wq,
                                                  const float* __restrict__ Wk,
                                                  const float* __restrict__ Wv,
                                                  const float* __restrict__ coW,
                                                  const float* __restrict__ cob,
                                                  float* __restrict__ mq,
                                                  float* __restrict__ mk,
                                                  float* __restrict__ mv,
                                                  float* __restrict__ co)
{
    int m0 = blockIdx.x * 128, n0 = blockIdx.y * 64;
    switch (blockIdx.z) {
    case 0: gemm_core<false,false,false,false>(Q,   nullptr, Wq,  nullptr, mq, AHC, HIDC, m0, n0, 0, HIDC); break;
    case 1: gemm_core<false,false,false,false>(Kin, nullptr, Wk,  nullptr, mk, AHC, HIDC, m0, n0, 0, HIDC); break;
    case 2: gemm_core<false,false,false,false>(V,   nullptr, Wv,  nullptr, mv, AHC, HIDC, m0, n0, 0, HIDC); break;
    default:gemm_core<false,true, false,false>(V,   nullptr, coW, cob,     co, AHC, HIDC, m0, n0, 0, HIDC); break;
    }
}

// pointwise conv GEMM: mkc = dwt @ pw_w^T + sep_b
__global__ void __launch_bounds__(256) gemm_pw(const float* __restrict__ dwt,
                                               const float* __restrict__ pw,
                                               const float* __restrict__ sb,
                                               float* __restrict__ mkc)
{
    gemm_core<true, true, false, false>(dwt, nullptr, pw, sb, mkc,
                                        AHC, HIDC, blockIdx.x * 128, blockIdx.y * 64, 0, HIDC);
}

// ck logits GEMM, split-K x3: partial_z = (mkc .* mq) @ ck_W[z-slice] (+ck_b on z=0)
__global__ void __launch_bounds__(256) gemm_ck(const float* __restrict__ mkc,
                                               const float* __restrict__ mq,
                                               const float* __restrict__ ckW,
                                               const float* __restrict__ ckb,
                                               float* __restrict__ ckp)
{
    int z = blockIdx.z;
    float* Cz = ckp + (size_t)z * (BB * SS * CKN);
    if (z == 0)
        gemm_core<false, true,  true, true>(mkc, mq, ckW, ckb, Cz,
                                            CKN, AHC, blockIdx.x * 128, 0, 0, 128);
    else
        gemm_core<false, false, true, true>(mkc, mq, ckW, nullptr, Cz,
                                            CKN, AHC, blockIdx.x * 128, 0, z * 128, z * 128 + 128);
}

// ck: sum 3 partials, softmax over KS=9, write g_ck
__global__ void __launch_bounds__(256) cksm_kernel()
{
    int row = blockIdx.x * 256 + threadIdx.x;     // BB*SS*HH rows
    if (row >= BB * SS * HH) return;
    const size_t R = (size_t)BB * SS * CKN;
    const float* p0 = g_ckp + (size_t)row * KSC;
    float v[KSC];
    float m = -3e38f;
#pragma unroll
    for (int k = 0; k < KSC; k++) {
        v[k] = p0[k] + p0[R + k] + p0[2 * R + k];
        m = fmaxf(m, v[k]);
    }
    float sum = 0.f;
#pragma unroll
    for (int k = 0; k < KSC; k++) { v[k] = expf(v[k] - m); sum += v[k]; }
    float invs = 1.f / sum;
    float* o = g_ck + (size_t)row * KSC;
#pragma unroll
    for (int k = 0; k < KSC; k++) o[k] = v[k] * invs;
}

// ---------------- depthwise conv over sequence (kernel 9, pad 4) ----------------
__global__ void __launch_bounds__(256) dw_kernel(const float* __restrict__ Kin,
                                                 const float* __restrict__ dw_w)
{
    int bs = blockIdx.x;              // b*S + s
    int b = bs >> 10, s = bs & 1023;
    for (int c = threadIdx.x; c < HIDC; c += 256) {
        float acc = 0.f;
#pragma unroll
        for (int k = 0; k < KSC; k++) {
            int sr = s + k - PADC;
            if (sr >= 0 && sr < SS)
                acc += Kin[(size_t)(b * SS + sr) * HIDC + c] * dw_w[c * KSC + k];
        }
        g_dwt[(size_t)bs * HIDC + c] = acc;
    }
}

// ---------------- conv_out: sliding-window gather of co weighted by ck ----------------
__global__ void __launch_bounds__(128) conv_out_kernel(float* __restrict__ out)
{
    int bs = blockIdx.x;
    int b = bs >> 10, s = bs & 1023;
    __shared__ float cks[CKN];
    if (threadIdx.x < CKN) cks[threadIdx.x] = g_ck[(size_t)bs * CKN + threadIdx.x];
    __syncthreads();
    for (int a = threadIdx.x; a < AHC; a += 128) {
        int h = a >> 6;
        float acc = 0.f;
#pragma unroll
        for (int k = 0; k < KSC; k++) {
            int sr = s + k - PADC;
            if (sr >= 0 && sr < SS)
                acc += g_co[(size_t)(b * SS + sr) * AHC + a] * cks[h * KSC + k];
        }
        out[(size_t)bs * OW + AHC + a] = acc;
    }
}

// ---------------- td softmax (independent of head and query row) ----------------
__global__ void __launch_bounds__(256) tdsm_kernel(const float* __restrict__ td,
                                                   const int* __restrict__ mask)
{
    __shared__ float red[8];
    __shared__ float bc;
    int b = blockIdx.x, tid = threadIdx.x;
    int wid = tid >> 5, ln = tid & 31;

    float ss = 0.f;
    for (int j = tid; j < SS; j += 256) { float v = td[b * SS + j]; ss += v * v; }
#pragma unroll
    for (int o = 16; o; o >>= 1) ss += __shfl_xor_sync(0xffffffffu, ss, o);
    if (ln == 0) red[wid] = ss;
    __syncthreads();
    if (tid == 0) {
        float t = 0.f;
        for (int k = 0; k < 8; k++) t += red[k];
        bc = 1.f / fmaxf(sqrtf(t), 1e-12f);
    }
    __syncthreads();
    float inv = bc;

    float m = -1e4f;
    for (int j = tid; j < SS; j += 256)
        if (mask[b * SS + j]) m = fmaxf(m, td[b * SS + j] * inv);
#pragma unroll
    for (int o = 16; o; o >>= 1) m = fmaxf(m, __shfl_xor_sync(0xffffffffu, m, o));
    if (ln == 0) red[wid] = m;
    __syncthreads();
    if (tid == 0) {
        float t = -1e4f;
        for (int k = 0; k < 8; k++) t = fmaxf(t, red[k]);
        bc = t;
    }
    __syncthreads();
    float mm = bc;
    __syncthreads();

    float den = 0.f;
    for (int j = tid; j < SS; j += 256)
        if (mask[b * SS + j]) den += expf(td[b * SS + j] * inv - mm);
#pragma unroll
    for (int o = 16; o; o >>= 1) den += __shfl_xor_sync(0xffffffffu, den, o);
    if (ln == 0) red[wid] = den;
    __syncthreads();
    if (tid == 0) {
        float t = 0.f;
        for (int k = 0; k < 8; k++) t += red[k];
        bc = 1.f / t;
    }
    __syncthreads();
    float invden = bc;

    for (int j = tid; j < SS; j += 256) {
        float v = mask[b * SS + j] ? expf(td[b * SS + j] * inv - mm) * invden : 0.f;
        g_tdsm[b * SS + j] = v;
    }
}

// ---------------- attention with distance decay ----------------
// grid (S/32, H, B); 8 warps x 4 query rows each = 32 rows/block.
// K/V staged in 128x66 smem (2-bank stride -> conflict-free .64 both ways).
// Score rows swizzled SIDX(j) = j + (j>>5).
__global__ void __launch_bounds__(256) attn_kernel(const int* __restrict__ mask,
                                                   const float* __restrict__ gammas,
                                                   float* __restrict__ out)
{
    extern __shared__ float sm[];
    float* kt  = sm;                       // 128*66
    float* sc  = kt + 128 * 66;            // 32*1056
    float* qs  = sc + 32 * 1056;           // 32*64
    float* msk = qs + 32 * 64;             // 1024
    float* tds = msk + 1024;               // 1024

    const int tid  = threadIdx.x;
    const int w    = tid >> 5, lane = tid & 31;
    const int i0   = blockIdx.x * TIQ;
    const int h    = blockIdx.y;
    const int b    = blockIdx.z;
    const int r0   = w * RPW;              // warp's first local row

    for (int j = tid; j < SS; j += 256) {
        msk[j] = mask[b * SS + j] ? 1.f : 0.f;
        tds[j] = g_tdsm[b * SS + j];
    }
    for (int idx = tid; idx < TIQ * 32; idx += 256) {   // 32 rows x 32 float2
        int r = idx >> 5, dp = idx & 31;
        *(float2*)&qs[r * 64 + 2 * dp] =
            *(const float2*)(g_mq + (size_t)(b * SS + i0 + r) * AHC + h * DD + 2 * dp);
    }
    float gv = gammas[h];
    float gamma = -(gv > 20.f ? gv : log1pf(expf(gv)));   // -softplus

    // ---- QK: scores for 4 rows x 128 j per warp per tile ----
    for (int jt = 0; jt < 8; jt++) {
        __syncthreads();
        for (int idx = tid; idx < 4096; idx += 256) {
            int r = idx >> 5, dp = idx & 31;
            *(float2*)&kt[r * 66 + 2 * dp] =
                *(const float2*)(g_mk + (size_t)(b * SS + jt * 128 + r) * AHC + h * DD + 2 * dp);
        }
        __syncthreads();
        ull acc[RPW][4];
#pragma unroll
        for (int rr = 0; rr < RPW; rr++)
#pragma unroll
            for (int c = 0; c < 4; c++) acc[rr][c] = 0ull;
#pragma unroll
        for (int dp = 0; dp < 32; dp++) {
            ull k0 = *(const ull*)&kt[(lane      ) * 66 + 2 * dp];
            ull k1 = *(const ull*)&kt[(lane +  32) * 66 + 2 * dp];
            ull k2 = *(const ull*)&kt[(lane +  64) * 66 + 2 * dp];
            ull k3 = *(const ull*)&kt[(lane +  96) * 66 + 2 * dp];
#pragma unroll
            for (int rr = 0; rr < RPW; rr++) {
                ull q2 = *(const ull*)&qs[(r0 + rr) * 64 + 2 * dp];
                ffma2(acc[rr][0], q2, k0);
                ffma2(acc[rr][1], q2, k1);
                ffma2(acc[rr][2], q2, k2);
                ffma2(acc[rr][3], q2, k3);
            }
        }
#pragma unroll
        for (int rr = 0; rr < RPW; rr++) {
            float* srow = sc + (r0 + rr) * 1056;
#pragma unroll
            for (int c = 0; c < 4; c++) {
                float lo, hi; unpack2(lo, hi, acc[rr][c]);
                int j = jt * 128 + c * 32 + lane;
                srow[j + (j >> 5)] = (lo + hi) * 0.125f;
            }
        }
    }
    __syncwarp();

    // ---- softmax / distance-decay passes, per row ----
    float invsv[RPW];
#pragma unroll
    for (int rr = 0; rr < RPW; rr++) {
        const int i = i0 + r0 + rr;
        float* srow = sc + (r0 + rr) * 1056;

        // pass 1: masked max (lane-strided)
        float m1 = -3e38f;
#pragma unroll
        for (int c = 0; c < 32; c++) {
            int j = c * 32 + lane;
            if (msk[j] != 0.f) m1 = fmaxf(m1, srow[c * 33 + lane]);
        }
#pragma unroll
        for (int o = 16; o; o >>= 1) m1 = fmaxf(m1, __shfl_xor_sync(0xffffffffu, m1, o));

        // pass 2: p ~ exp * mask, inclusive cumsum (lane-contiguous chunk)
        float cuml[32];
        float run = 0.f;
#pragma unroll
        for (int c = 0; c < 32; c++) {
            int j = lane * 32 + c;
            float p = (msk[j] != 0.f) ? expf(srow[lane * 33 + c] - m1) : 0.f;
            run += p;
            cuml[c] = run;
        }
        float v = run;
#pragma unroll
        for (int o = 1; o < 32; o <<= 1) {
            float t = __shfl_up_sync(0xffffffffu, v, o);
            if (lane >= o) v += t;
        }
        float total = __shfl_sync(0xffffffffu, v, 31);
        float off = v - run;
        float invtot = 1.f / fmaxf(total, 1e-30f);

        // pass 3: total_effect, modified scores, max
        float m2 = -3e38f;
#pragma unroll
        for (int c = 0; c < 32; c++) {
            int j = lane * 32 + c;
            float s2;
            if (msk[j] != 0.f) {
                float cum = cuml[c] + off;
                float pos = fabsf((float)(j - i));
                float rem = (total - cum) * invtot;
                float ds = sqrtf(fmaxf(rem * pos, 0.f));
                float te = expf(gamma * ds);
                te = fminf(fmaxf(te, 1e-5f), 1e5f);
                if (j < i) te -= tds[j];
                s2 = srow[lane * 33 + c] * te;
            } else {
                s2 = -1e8f;
            }
            srow[lane * 33 + c] = s2;
            m2 = fmaxf(m2, s2);
        }
#pragma unroll
        for (int o = 16; o; o >>= 1) m2 = fmaxf(m2, __shfl_xor_sync(0xffffffffu, m2, o));

        // pass 4: exp + sum
        float sum2 = 0.f;
#pragma unroll
        for (int c = 0; c < 32; c++) {
            float e = expf(srow[lane * 33 + c] - m2);
            srow[lane * 33 + c] = e;
            sum2 += e;
        }
#pragma unroll
        for (int o = 16; o; o >>= 1) sum2 += __shfl_xor_sync(0xffffffffu, sum2, o);
        invsv[rr] = 1.f / sum2;
    }

    // ---- PV: lane owns d = 2*lane, 2*lane+1; 4 rows per warp ----
    ull accd[RPW];
#pragma unroll
    for (int rr = 0; rr < RPW; rr++) accd[rr] = 0ull;
    const float* s0 = sc + r0 * 1056;
    for (int jt = 0; jt < 8; jt++) {
        __syncthreads();
        for (int idx = tid; idx < 4096; idx += 256) {
            int r = idx >> 5, dp = idx & 31;
            *(float2*)&kt[r * 66 + 2 * dp] =
                *(const float2*)(g_mv + (size_t)(b * SS + jt * 128 + r) * AHC + h * DD + 2 * dp);
        }
        __syncthreads();
        int jb = jt * 128;
#pragma unroll 8
        for (int jl = 0; jl < 128; jl++) {
            int j = jb + jl;
            int sidx = j + (j >> 5);
            ull kv = *(const ull*)&kt[jl * 66 + 2 * lane];
#pragma unroll
            for (int rr = 0; rr < RPW; rr++) {
                float pr = s0[rr * 1056 + sidx];
                ffma2(accd[rr], pack2(pr, pr), kv);
            }
        }
    }
#pragma unroll
    for (int rr = 0; rr < RPW; rr++) {
        float lo, hi; unpack2(lo, hi, accd[rr]);
        size_t ob = (size_t)(b * SS + i0 + r0 + rr) * OW + h * DD;
        *(float2*)(out + ob + 2 * lane) = make_float2(lo * invsv[rr], hi * invsv[rr]);
    }
}

// ---------------- launch ----------------
extern "C" void kernel_launch(void* const* d_in, const int* in_sizes, int n_in,
                              void* d_out, int out_size)
{
    const float* Q      = (const float*)d_in[0];
    const float* Kin    = (const float*)d_in[1];
    const float* V      = (const float*)d_in[2];
    const float* td     = (const float*)d_in[3];
    const int*   mask   = (const int*)  d_in[4];
    const float* Wq     = (const float*)d_in[5];
    const float* Wk     = (const float*)d_in[6];
    const float* Wv     = (const float*)d_in[7];
    const float* dw_w   = (const float*)d_in[8];
    const float* pw_w   = (const float*)d_in[9];
    const float* sep_b  = (const float*)d_in[10];
    const float* ck_W   = (const float*)d_in[11];
    const float* ck_b   = (const float*)d_in[12];
    const float* co_W   = (const float*)d_in[13];
    const float* co_b   = (const float*)d_in[14];
    const float* gammas = (const float*)d_in[15];
    float* out = (float*)d_out;

    float *p_mq, *p_mk, *p_mv, *p_co, *p_mkc, *p_dwt, *p_ckp;
    cudaGetSymbolAddress((void**)&p_mq,  g_mq);
    cudaGetSymbolAddress((void**)&p_mk,  g_mk);
    cudaGetSymbolAddress((void**)&p_mv,  g_mv);
    cudaGetSymbolAddress((void**)&p_co,  g_co);
    cudaGetSymbolAddress((void**)&p_mkc, g_mkc);
    cudaGetSymbolAddress((void**)&p_dwt, g_dwt);
    cudaGetSymbolAddress((void**)&p_ckp, g_ckp);

    const int M = BB * SS;

    gemm_fused<<<dim3(M / 128, AHC / 64, 4), 256>>>(Q, Kin, V, Wq, Wk, Wv, co_W, co_b,
                                                    p_mq, p_mk, p_mv, p_co);

    dw_kernel<<<BB * SS, 256>>>(Kin, dw_w);
    gemm_pw<<<dim3(M / 128, AHC / 64), 256>>>(p_dwt, pw_w, sep_b, p_mkc);

    gemm_ck<<<dim3(M / 128, 1, 3), 256>>>(p_mkc, p_mq, ck_W, ck_b, p_ckp);
    cksm_kernel<<<(BB * SS * HH + 255) / 256, 256>>>();
    conv_out_kernel<<<BB * SS, 128>>>(out);

    tdsm_kernel<<<BB, 256>>>(td, mask);

    int smem = (128 * 66 + 32 * 1056 + 32 * 64 + 1024 + 1024) * (int)sizeof(float);
    cudaFuncSetAttribute(attn_kernel, cudaFuncAttributeMaxDynamicSharedMemorySize, smem);
    attn_kernel<<<dim3(SS / TIQ, HH, BB), 256, smem>>>(mask, gammas, out);
}

// round 5
// speedup vs baseline: 1.2909x; 1.0954x over previous
#include <cuda_runtime.h>
#include <math.h>

#define BB   4
#define SS   1024
#define HIDC 768
#define HH   6
#define DD   64
#define AHC  384
#define KSC  9
#define PADC 4
#define OW   768   // output width = 2*AH
#define CKN  54    // H*KS
#define TIQ  32    // query rows per attention block
#define RPW  2     // query rows per warp (16 warps)
#define ATHR 512   // attention block threads
#define CKZ  6     // split-K factor for ck GEMM

typedef unsigned long long ull;

// ---------------- f32x2 packed helpers ----------------
__device__ __forceinline__ void ffma2(ull& d, ull a, ull b) {
    asm("fma.rn.f32x2 %0, %1, %2, %3;" : "=l"(d) : "l"(a), "l"(b), "l"(d));
}
__device__ __forceinline__ ull pack2(float lo, float hi) {
    ull r; asm("mov.b64 %0, {%1, %2};" : "=l"(r) : "f"(lo), "f"(hi)); return r;
}
__device__ __forceinline__ void unpack2(float& lo, float& hi, ull v) {
    asm("mov.b64 {%0, %1}, %2;" : "=f"(lo), "=f"(hi) : "l"(v));
}

// ---------------- scratch (device globals: no allocations allowed) ----------------
__device__ float g_mq [BB*SS*AHC];
__device__ float g_mk [BB*SS*AHC];
__device__ float g_mv [BB*SS*AHC];
__device__ float g_co [BB*SS*AHC];
__device__ float g_mkc[BB*SS*AHC];
__device__ float g_dwt[BB*SS*HIDC];
__device__ float g_ck [BB*SS*CKN];
__device__ float g_ckp[CKZ*BB*SS*CKN];   // split-K partials for ck logits
__device__ float g_tdsm[BB*SS];

// ---------------- GEMM core: C[M,N] = A[M,K] @ B (+bias), 128x64 tile, f32x2 ----------------
template<bool BT, bool BIAS, bool NGUARD, bool AMUL>
__device__ __forceinline__ void gemm_core(const float* __restrict__ A,
                                          const float* __restrict__ A2,
                                          const float* __restrict__ Bm,
                                          const float* __restrict__ bias,
                                          float* __restrict__ C,
                                          int N, int K, int m0, int n0,
                                          int kBeg, int kEnd)
{
    __shared__ float As[16][128];
    __shared__ float Bs[16][64];
    const int tid = threadIdx.x;
    const int ty = tid >> 4, tx = tid & 15;
    const int lr = tid >> 1, lk = (tid & 1) * 8;

    ull acc[8][2];
#pragma unroll
    for (int i = 0; i < 8; i++) { acc[i][0] = 0ull; acc[i][1] = 0ull; }

    for (int k0 = kBeg; k0 < kEnd; k0 += 16) {
        {
            const float* ap = A + (size_t)(m0 + lr) * K + k0 + lk;
            float4 a0 = *(const float4*)(ap);
            float4 a1 = *(const float4*)(ap + 4);
            if (AMUL) {
                const float* a2p = A2 + (size_t)(m0 + lr) * K + k0 + lk;
                float4 m0v = *(const float4*)(a2p);
                float4 m1v = *(const float4*)(a2p + 4);
                a0.x *= m0v.x; a0.y *= m0v.y; a0.z *= m0v.z; a0.w *= m0v.w;
                a1.x *= m1v.x; a1.y *= m1v.y; a1.z *= m1v.z; a1.w *= m1v.w;
            }
            As[lk + 0][lr] = a0.x; As[lk + 1][lr] = a0.y;
            As[lk + 2][lr] = a0.z; As[lk + 3][lr] = a0.w;
            As[lk + 4][lr] = a1.x; As[lk + 5][lr] = a1.y;
            As[lk + 6][lr] = a1.z; As[lk + 7][lr] = a1.w;
        }
        if (!BT) {
            int bk = tid >> 4, bn = (tid & 15) * 4;
            if (!NGUARD) {
                float4 bv = *(const float4*)(Bm + (size_t)(k0 + bk) * N + n0 + bn);
                Bs[bk][bn + 0] = bv.x; Bs[bk][bn + 1] = bv.y;
                Bs[bk][bn + 2] = bv.z; Bs[bk][bn + 3] = bv.w;
            } else {
#pragma unroll
                for (int j = 0; j < 4; j++) {
                    int n = n0 + bn + j;
                    Bs[bk][bn + j] = (n < N) ? Bm[(size_t)(k0 + bk) * N + n] : 0.f;
                }
            }
        } else {
            int bn = tid >> 2, bkk = (tid & 3) * 4;
            float4 bv = *(const float4*)(Bm + (size_t)(n0 + bn) * K + k0 + bkk);
            Bs[bkk + 0][bn] = bv.x; Bs[bkk + 1][bn] = bv.y;
            Bs[bkk + 2][bn] = bv.z; Bs[bkk + 3][bn] = bv.w;
        }
        __syncthreads();
#pragma unroll
        for (int k = 0; k < 16; k++) {
            float4 aA = *(const float4*)&As[k][ty * 8];
            float4 aB = *(const float4*)&As[k][ty * 8 + 4];
            ull b01 = *(const ull*)&Bs[k][tx * 4];
            ull b23 = *(const ull*)&Bs[k][tx * 4 + 2];
            ull ap;
            ap = pack2(aA.x, aA.x); ffma2(acc[0][0], ap, b01); ffma2(acc[0][1], ap, b23);
            ap = pack2(aA.y, aA.y); ffma2(acc[1][0], ap, b01); ffma2(acc[1][1], ap, b23);
            ap = pack2(aA.z, aA.z); ffma2(acc[2][0], ap, b01); ffma2(acc[2][1], ap, b23);
            ap = pack2(aA.w, aA.w); ffma2(acc[3][0], ap, b01); ffma2(acc[3][1], ap, b23);
            ap = pack2(aB.x, aB.x); ffma2(acc[4][0], ap, b01); ffma2(acc[4][1], ap, b23);
            ap = pack2(aB.y, aB.y); ffma2(acc[5][0], ap, b01); ffma2(acc[5][1], ap, b23);
            ap = pack2(aB.z, aB.z); ffma2(acc[6][0], ap, b01); ffma2(acc[6][1], ap, b23);
            ap = pack2(aB.w, aB.w); ffma2(acc[7][0], ap, b01); ffma2(acc[7][1], ap, b23);
        }
        __syncthreads();
    }
#pragma unroll
    for (int i = 0; i < 8; i++) {
        int m = m0 + ty * 8 + i;
#pragma unroll
        for (int p = 0; p < 2; p++) {
            float lo, hi; unpack2(lo, hi, acc[i][p]);
            int n = n0 + tx * 4 + 2 * p;
            if (!NGUARD || n < N) {
                float v = lo; if (BIAS) v += bias[n];
                C[(size_t)m * N + n] = v;
            }
            if (!NGUARD || n + 1 < N) {
                float v = hi; if (BIAS) v += bias[n + 1];
                C[(size_t)m * N + n + 1] = v;
            }
        }
    }
}

// fused 4-way projection GEMM: z selects (A, B, bias, C)
__global__ void __launch_bounds__(256) gemm_fused(const float* __restrict__ Q,
                                                  const float* __restrict__ Kin,
                                                  const float* __restrict__ V,
                                                  const float* __restrict__ Wq,
                                                  const float* __restrict__ Wk,
                                                  const float* __restrict__ Wv,
                                                  const float* __restrict__ coW,
                                                  const float* __restrict__ cob,
                                                  float* __restrict__ mq,
                                                  float* __restrict__ mk,
                                                  float* __restrict__ mv,
                                                  float* __restrict__ co)
{
    int m0 = blockIdx.x * 128, n0 = blockIdx.y * 64;
    switch (blockIdx.z) {
    case 0: gemm_core<false,false,false,false>(Q,   nullptr, Wq,  nullptr, mq, AHC, HIDC, m0, n0, 0, HIDC); break;
    case 1: gemm_core<false,false,false,false>(Kin, nullptr, Wk,  nullptr, mk, AHC, HIDC, m0, n0, 0, HIDC); break;
    case 2: gemm_core<false,false,false,false>(V,   nullptr, Wv,  nullptr, mv, AHC, HIDC, m0, n0, 0, HIDC); break;
    default:gemm_core<false,true, false,false>(V,   nullptr, coW, cob,     co, AHC, HIDC, m0, n0, 0, HIDC); break;
    }
}

// pointwise conv GEMM: mkc = dwt @ pw_w^T + sep_b
__global__ void __launch_bounds__(256) gemm_pw(const float* __restrict__ dwt,
                                               const float* __restrict__ pw,
                                               const float* __restrict__ sb,
                                               float* __restrict__ mkc)
{
    gemm_core<true, true, false, false>(dwt, nullptr, pw, sb, mkc,
                                        AHC, HIDC, blockIdx.x * 128, blockIdx.y * 64, 0, HIDC);
}

// ck logits GEMM, split-K x CKZ
__global__ void __launch_bounds__(256) gemm_ck(const float* __restrict__ mkc,
                                               const float* __restrict__ mq,
                                               const float* __restrict__ ckW,
                                               const float* __restrict__ ckb,
                                               float* __restrict__ ckp)
{
    int z = blockIdx.z;
    const int KS_ = AHC / CKZ;   // 64
    float* Cz = ckp + (size_t)z * (BB * SS * CKN);
    if (z == 0)
        gemm_core<false, true,  true, true>(mkc, mq, ckW, ckb, Cz,
                                            CKN, AHC, blockIdx.x * 128, 0, 0, KS_);
    else
        gemm_core<false, false, true, true>(mkc, mq, ckW, nullptr, Cz,
                                            CKN, AHC, blockIdx.x * 128, 0, z * KS_, z * KS_ + KS_);
}

// ck: sum CKZ partials, softmax over KS=9, write g_ck
__global__ void __launch_bounds__(256) cksm_kernel()
{
    int row = blockIdx.x * 256 + threadIdx.x;     // BB*SS*HH rows
    if (row >= BB * SS * HH) return;
    const size_t R = (size_t)BB * SS * CKN;
    const float* p0 = g_ckp + (size_t)row * KSC;
    float v[KSC];
    float m = -3e38f;
#pragma unroll
    for (int k = 0; k < KSC; k++) {
        float s = 0.f;
#pragma unroll
        for (int z = 0; z < CKZ; z++) s += p0[z * R + k];
        v[k] = s;
        m = fmaxf(m, s);
    }
    float sum = 0.f;
#pragma unroll
    for (int k = 0; k < KSC; k++) { v[k] = expf(v[k] - m); sum += v[k]; }
    float invs = 1.f / sum;
    float* o = g_ck + (size_t)row * KSC;
#pragma unroll
    for (int k = 0; k < KSC; k++) o[k] = v[k] * invs;
}

// ---------------- depthwise conv over sequence (kernel 9, pad 4) ----------------
__global__ void __launch_bounds__(256) dw_kernel(const float* __restrict__ Kin,
                                                 const float* __restrict__ dw_w)
{
    int bs = blockIdx.x;              // b*S + s
    int b = bs >> 10, s = bs & 1023;
    for (int c = threadIdx.x; c < HIDC; c += 256) {
        float acc = 0.f;
#pragma unroll
        for (int k = 0; k < KSC; k++) {
            int sr = s + k - PADC;
            if (sr >= 0 && sr < SS)
                acc += Kin[(size_t)(b * SS + sr) * HIDC + c] * dw_w[c * KSC + k];
        }
        g_dwt[(size_t)bs * HIDC + c] = acc;
    }
}

// ---------------- conv_out: sliding-window gather of co weighted by ck ----------------
__global__ void __launch_bounds__(128) conv_out_kernel(float* __restrict__ out)
{
    int bs = blockIdx.x;
    int b = bs >> 10, s = bs & 1023;
    __shared__ float cks[CKN];
    if (threadIdx.x < CKN) cks[threadIdx.x] = g_ck[(size_t)bs * CKN + threadIdx.x];
    __syncthreads();
    for (int a = threadIdx.x; a < AHC; a += 128) {
        int h = a >> 6;
        float acc = 0.f;
#pragma unroll
        for (int k = 0; k < KSC; k++) {
            int sr = s + k - PADC;
            if (sr >= 0 && sr < SS)
                acc += g_co[(size_t)(b * SS + sr) * AHC + a] * cks[h * KSC + k];
        }
        out[(size_t)bs * OW + AHC + a] = acc;
    }
}

// ---------------- td softmax (independent of head and query row) ----------------
__global__ void __launch_bounds__(256) tdsm_kernel(const float* __restrict__ td,
                                                   const int* __restrict__ mask)
{
    __shared__ float red[8];
    __shared__ float bc;
    int b = blockIdx.x, tid = threadIdx.x;
    int wid = tid >> 5, ln = tid & 31;

    float ss = 0.f;
    for (int j = tid; j < SS; j += 256) { float v = td[b * SS + j]; ss += v * v; }
#pragma unroll
    for (int o = 16; o; o >>= 1) ss += __shfl_xor_sync(0xffffffffu, ss, o);
    if (ln == 0) red[wid] = ss;
    __syncthreads();
    if (tid == 0) {
        float t = 0.f;
        for (int k = 0; k < 8; k++) t += red[k];
        bc = 1.f / fmaxf(sqrtf(t), 1e-12f);
    }
    __syncthreads();
    float inv = bc;

    float m = -1e4f;
    for (int j = tid; j < SS; j += 256)
        if (mask[b * SS + j]) m = fmaxf(m, td[b * SS + j] * inv);
#pragma unroll
    for (int o = 16; o; o >>= 1) m = fmaxf(m, __shfl_xor_sync(0xffffffffu, m, o));
    if (ln == 0) red[wid] = m;
    __syncthreads();
    if (tid == 0) {
        float t = -1e4f;
        for (int k = 0; k < 8; k++) t = fmaxf(t, red[k]);
        bc = t;
    }
    __syncthreads();
    float mm = bc;
    __syncthreads();

    float den = 0.f;
    for (int j = tid; j < SS; j += 256)
        if (mask[b * SS + j]) den += expf(td[b * SS + j] * inv - mm);
#pragma unroll
    for (int o = 16; o; o >>= 1) den += __shfl_xor_sync(0xffffffffu, den, o);
    if (ln == 0) red[wid] = den;
    __syncthreads();
    if (tid == 0) {
        float t = 0.f;
        for (int k = 0; k < 8; k++) t += red[k];
        bc = 1.f / t;
    }
    __syncthreads();
    float invden = bc;

    for (int j = tid; j < SS; j += 256) {
        float v = mask[b * SS + j] ? expf(td[b * SS + j] * inv - mm) * invden : 0.f;
        g_tdsm[b * SS + j] = v;
    }
}

// ---------------- attention with distance decay ----------------
// grid (S/32, H, B); 16 warps x 2 query rows each = 32 rows/block.
// K/V staged in 128x66 smem (2-bank stride -> conflict-free .64 both ways).
// Score rows swizzled SIDX(j) = j + (j>>5).
__global__ void __launch_bounds__(ATHR) attn_kernel(const int* __restrict__ mask,
                                                    const float* __restrict__ gammas,
                                                    float* __restrict__ out)
{
    extern __shared__ float sm[];
    float* kt  = sm;                       // 128*66
    float* sc  = kt + 128 * 66;            // 32*1056
    float* qs  = sc + 32 * 1056;           // 32*64
    float* msk = qs + 32 * 64;             // 1024
    float* tds = msk + 1024;               // 1024

    const int tid  = threadIdx.x;
    const int w    = tid >> 5, lane = tid & 31;
    const int i0   = blockIdx.x * TIQ;
    const int h    = blockIdx.y;
    const int b    = blockIdx.z;
    const int r0   = w * RPW;              // warp's first local row

    for (int j = tid; j < SS; j += ATHR) {
        msk[j] = mask[b * SS + j] ? 1.f : 0.f;
        tds[j] = g_tdsm[b * SS + j];
    }
    for (int idx = tid; idx < TIQ * 32; idx += ATHR) {   // 32 rows x 32 float2
        int r = idx >> 5, dp = idx & 31;
        *(float2*)&qs[r * 64 + 2 * dp] =
            *(const float2*)(g_mq + (size_t)(b * SS + i0 + r) * AHC + h * DD + 2 * dp);
    }
    float gv = gammas[h];
    float gamma = -(gv > 20.f ? gv : log1pf(expf(gv)));   // -softplus

    // ---- QK: scores for 2 rows x 128 j per warp per tile ----
    for (int jt = 0; jt < 8; jt++) {
        __syncthreads();
        for (int idx = tid; idx < 4096; idx += ATHR) {
            int r = idx >> 5, dp = idx & 31;
            *(float2*)&kt[r * 66 + 2 * dp] =
                *(const float2*)(g_mk + (size_t)(b * SS + jt * 128 + r) * AHC + h * DD + 2 * dp);
        }
        __syncthreads();
        ull acc[RPW][4];
#pragma unroll
        for (int rr = 0; rr < RPW; rr++)
#pragma unroll
            for (int c = 0; c < 4; c++) acc[rr][c] = 0ull;
#pragma unroll
        for (int dp = 0; dp < 32; dp++) {
            ull k0 = *(const ull*)&kt[(lane      ) * 66 + 2 * dp];
            ull k1 = *(const ull*)&kt[(lane +  32) * 66 + 2 * dp];
            ull k2 = *(const ull*)&kt[(lane +  64) * 66 + 2 * dp];
            ull k3 = *(const ull*)&kt[(lane +  96) * 66 + 2 * dp];
#pragma unroll
            for (int rr = 0; rr < RPW; rr++) {
                ull q2 = *(const ull*)&qs[(r0 + rr) * 64 + 2 * dp];
                ffma2(acc[rr][0], q2, k0);
                ffma2(acc[rr][1], q2, k1);
                ffma2(acc[rr][2], q2, k2);
                ffma2(acc[rr][3], q2, k3);
            }
        }
#pragma unroll
        for (int rr = 0; rr < RPW; rr++) {
            float* srow = sc + (r0 + rr) * 1056;
#pragma unroll
            for (int c = 0; c < 4; c++) {
                float lo, hi; unpack2(lo, hi, acc[rr][c]);
                int j = jt * 128 + c * 32 + lane;
                srow[j + (j >> 5)] = (lo + hi) * 0.125f;
            }
        }
    }
    __syncwarp();

    // ---- softmax / distance-decay passes, per row ----
    float invsv[RPW];
#pragma unroll
    for (int rr = 0; rr < RPW; rr++) {
        const int i = i0 + r0 + rr;
        float* srow = sc + (r0 + rr) * 1056;

        // pass 1: masked max (lane-strided)
        float m1 = -3e38f;
#pragma unroll
        for (int c = 0; c < 32; c++) {
            int j = c * 32 + lane;
            if (msk[j] != 0.f) m1 = fmaxf(m1, srow[c * 33 + lane]);
        }
#pragma unroll
        for (int o = 16; o; o >>= 1) m1 = fmaxf(m1, __shfl_xor_sync(0xffffffffu, m1, o));

        // pass 2: p ~ exp * mask, inclusive cumsum (lane-contiguous chunk)
        float cuml[32];
        float run = 0.f;
#pragma unroll
        for (int c = 0; c < 32; c++) {
            int j = lane * 32 + c;
            float p = (msk[j] != 0.f) ? expf(srow[lane * 33 + c] - m1) : 0.f;
            run += p;
            cuml[c] = run;
        }
        float v = run;
#pragma unroll
        for (int o = 1; o < 32; o <<= 1) {
            float t = __shfl_up_sync(0xffffffffu, v, o);
            if (lane >= o) v += t;
        }
        float total = __shfl_sync(0xffffffffu, v, 31);
        float off = v - run;
        float invtot = 1.f / fmaxf(total, 1e-30f);

        // pass 3: total_effect, modified scores, max
        float m2 = -3e38f;
#pragma unroll
        for (int c = 0; c < 32; c++) {
            int j = lane * 32 + c;
            float s2;
            if (msk[j] != 0.f) {
                float cum = cuml[c] + off;
                float pos = fabsf((float)(j - i));
                float rem = (total - cum) * invtot;
                float ds = sqrtf(fmaxf(rem * pos, 0.f));
                float te = expf(gamma * ds);
                te = fminf(fmaxf(te, 1e-5f), 1e5f);
                if (j < i) te -= tds[j];
                s2 = srow[lane * 33 + c] * te;
            } else {
                s2 = -1e8f;
            }
            srow[lane * 33 + c] = s2;
            m2 = fmaxf(m2, s2);
        }
#pragma unroll
        for (int o = 16; o; o >>= 1) m2 = fmaxf(m2, __shfl_xor_sync(0xffffffffu, m2, o));

        // pass 4: exp + sum
        float sum2 = 0.f;
#pragma unroll
        for (int c = 0; c < 32; c++) {
            float e = expf(srow[lane * 33 + c] - m2);
            srow[lane * 33 + c] = e;
            sum2 += e;
        }
#pragma unroll
        for (int o = 16; o; o >>= 1) sum2 += __shfl_xor_sync(0xffffffffu, sum2, o);
        invsv[rr] = 1.f / sum2;
    }

    // ---- PV: lane owns d = 2*lane, 2*lane+1; RPW rows per warp ----
    ull accd[RPW];
#pragma unroll
    for (int rr = 0; rr < RPW; rr++) accd[rr] = 0ull;
    const float* s0 = sc + r0 * 1056;
    for (int jt = 0; jt < 8; jt++) {
        __syncthreads();
        for (int idx = tid; idx < 4096; idx += ATHR) {
            int r = idx >> 5, dp = idx & 31;
            *(float2*)&kt[r * 66 + 2 * dp] =
                *(const float2*)(g_mv + (size_t)(b * SS + jt * 128 + r) * AHC + h * DD + 2 * dp);
        }
        __syncthreads();
        int jb = jt * 128;
#pragma unroll 8
        for (int jl = 0; jl < 128; jl++) {
            int j = jb + jl;
            int sidx = j + (j >> 5);
            ull kv = *(const ull*)&kt[jl * 66 + 2 * lane];
#pragma unroll
            for (int rr = 0; rr < RPW; rr++) {
                float pr = s0[rr * 1056 + sidx];
                ffma2(accd[rr], pack2(pr, pr), kv);
            }
        }
    }
#pragma unroll
    for (int rr = 0; rr < RPW; rr++) {
        float lo, hi; unpack2(lo, hi, accd[rr]);
        size_t ob = (size_t)(b * SS + i0 + r0 + rr) * OW + h * DD;
        *(float2*)(out + ob + 2 * lane) = make_float2(lo * invsv[rr], hi * invsv[rr]);
    }
}

// ---------------- launch ----------------
extern "C" void kernel_launch(void* const* d_in, const int* in_sizes, int n_in,
                              void* d_out, int out_size)
{
    const float* Q      = (const float*)d_in[0];
    const float* Kin    = (const float*)d_in[1];
    const float* V      = (const float*)d_in[2];
    const float* td     = (const float*)d_in[3];
    const int*   mask   = (const int*)  d_in[4];
    const float* Wq     = (const float*)d_in[5];
    const float* Wk     = (const float*)d_in[6];
    const float* Wv     = (const float*)d_in[7];
    const float* dw_w   = (const float*)d_in[8];
    const float* pw_w   = (const float*)d_in[9];
    const float* sep_b  = (const float*)d_in[10];
    const float* ck_W   = (const float*)d_in[11];
    const float* ck_b   = (const float*)d_in[12];
    const float* co_W   = (const float*)d_in[13];
    const float* co_b   = (const float*)d_in[14];
    const float* gammas = (const float*)d_in[15];
    float* out = (float*)d_out;

    float *p_mq, *p_mk, *p_mv, *p_co, *p_mkc, *p_dwt, *p_ckp;
    cudaGetSymbolAddress((void**)&p_mq,  g_mq);
    cudaGetSymbolAddress((void**)&p_mk,  g_mk);
    cudaGetSymbolAddress((void**)&p_mv,  g_mv);
    cudaGetSymbolAddress((void**)&p_co,  g_co);
    cudaGetSymbolAddress((void**)&p_mkc, g_mkc);
    cudaGetSymbolAddress((void**)&p_dwt, g_dwt);
    cudaGetSymbolAddress((void**)&p_ckp, g_ckp);

    const int M = BB * SS;

    // launch order arranged so attn_kernel is the 4th launch (ncu captures #4)
    tdsm_kernel<<<BB, 256>>>(td, mask);                                             // 1
    gemm_fused<<<dim3(M / 128, AHC / 64, 4), 256>>>(Q, Kin, V, Wq, Wk, Wv,          // 2
                                                    co_W, co_b, p_mq, p_mk, p_mv, p_co);
    dw_kernel<<<BB * SS, 256>>>(Kin, dw_w);                                         // 3

    int smem = (128 * 66 + 32 * 1056 + 32 * 64 + 1024 + 1024) * (int)sizeof(float);
    cudaFuncSetAttribute(attn_kernel, cudaFuncAttributeMaxDynamicSharedMemorySize, smem);
    attn_kernel<<<dim3(SS / TIQ, HH, BB), ATHR, smem>>>(mask, gammas, out);         // 4

    gemm_pw<<<dim3(M / 128, AHC / 64), 256>>>(p_dwt, pw_w, sep_b, p_mkc);           // 5
    gemm_ck<<<dim3(M / 128, 1, CKZ), 256>>>(p_mkc, p_mq, ck_W, ck_b, p_ckp);        // 6
    cksm_kernel<<<(BB * SS * HH + 255) / 256, 256>>>();                             // 7
    conv_out_kernel<<<BB * SS, 128>>>(out);                                         // 8
}

// round 6
// speedup vs baseline: 1.4964x; 1.1592x over previous
#include <cuda_runtime.h>
#include <math.h>

#define BB   4
#define SS   1024
#define HIDC 768
#define HH   6
#define DD   64
#define AHC  384
#define KSC  9
#define PADC 4
#define OW   768   // output width = 2*AH
#define CKN  54    // H*KS
#define TIQ  16    // query rows per attention block
#define RPW  2     // query rows per warp (8 warps)
#define ATHR 256   // attention block threads
#define CKZ  6     // split-K factor for ck GEMM

typedef unsigned long long ull;

// ---------------- f32x2 packed helpers ----------------
__device__ __forceinline__ void ffma2(ull& d, ull a, ull b) {
    asm("fma.rn.f32x2 %0, %1, %2, %3;" : "=l"(d) : "l"(a), "l"(b), "l"(d));
}
__device__ __forceinline__ ull pack2(float lo, float hi) {
    ull r; asm("mov.b64 %0, {%1, %2};" : "=l"(r) : "f"(lo), "f"(hi)); return r;
}
__device__ __forceinline__ void unpack2(float& lo, float& hi, ull v) {
    asm("mov.b64 {%0, %1}, %2;" : "=f"(lo), "=f"(hi) : "l"(v));
}

// ---------------- scratch (device globals: no allocations allowed) ----------------
__device__ float g_mq [BB*SS*AHC];
__device__ float g_mk [BB*SS*AHC];
__device__ float g_mv [BB*SS*AHC];
__device__ float g_co [BB*SS*AHC];
__device__ float g_mkc[BB*SS*AHC];
__device__ float g_dwt[BB*SS*HIDC];
__device__ float g_ck [BB*SS*CKN];
__device__ float g_ckp[CKZ*BB*SS*CKN];   // split-K partials for ck logits
__device__ float g_tdsm[BB*SS];

// ---------------- GEMM core: C[M,N] = A[M,K] @ B (+bias), 128x64 tile, f32x2 ----------------
template<bool BT, bool BIAS, bool NGUARD, bool AMUL>
__device__ __forceinline__ void gemm_core(const float* __restrict__ A,
                                          const float* __restrict__ A2,
                                          const float* __restrict__ Bm,
                                          const float* __restrict__ bias,
                                          float* __restrict__ C,
                                          int N, int K, int m0, int n0,
                                          int kBeg, int kEnd)
{
    __shared__ float As[16][128];
    __shared__ float Bs[16][64];
    const int tid = threadIdx.x;
    const int ty = tid >> 4, tx = tid & 15;
    const int lr = tid >> 1, lk = (tid & 1) * 8;

    ull acc[8][2];
#pragma unroll
    for (int i = 0; i < 8; i++) { acc[i][0] = 0ull; acc[i][1] = 0ull; }

    for (int k0 = kBeg; k0 < kEnd; k0 += 16) {
        {
            const float* ap = A + (size_t)(m0 + lr) * K + k0 + lk;
            float4 a0 = *(const float4*)(ap);
            float4 a1 = *(const float4*)(ap + 4);
            if (AMUL) {
                const float* a2p = A2 + (size_t)(m0 + lr) * K + k0 + lk;
                float4 m0v = *(const float4*)(a2p);
                float4 m1v = *(const float4*)(a2p + 4);
                a0.x *= m0v.x; a0.y *= m0v.y; a0.z *= m0v.z; a0.w *= m0v.w;
                a1.x *= m1v.x; a1.y *= m1v.y; a1.z *= m1v.z; a1.w *= m1v.w;
            }
            As[lk + 0][lr] = a0.x; As[lk + 1][lr] = a0.y;
            As[lk + 2][lr] = a0.z; As[lk + 3][lr] = a0.w;
            As[lk + 4][lr] = a1.x; As[lk + 5][lr] = a1.y;
            As[lk + 6][lr] = a1.z; As[lk + 7][lr] = a1.w;
        }
        if (!BT) {
            int bk = tid >> 4, bn = (tid & 15) * 4;
            if (!NGUARD) {
                float4 bv = *(const float4*)(Bm + (size_t)(k0 + bk) * N + n0 + bn);
                Bs[bk][bn + 0] = bv.x; Bs[bk][bn + 1] = bv.y;
                Bs[bk][bn + 2] = bv.z; Bs[bk][bn + 3] = bv.w;
            } else {
#pragma unroll
                for (int j = 0; j < 4; j++) {
                    int n = n0 + bn + j;
                    Bs[bk][bn + j] = (n < N) ? Bm[(size_t)(k0 + bk) * N + n] : 0.f;
                }
            }
        } else {
            int bn = tid >> 2, bkk = (tid & 3) * 4;
            float4 bv = *(const float4*)(Bm + (size_t)(n0 + bn) * K + k0 + bkk);
            Bs[bkk + 0][bn] = bv.x; Bs[bkk + 1][bn] = bv.y;
            Bs[bkk + 2][bn] = bv.z; Bs[bkk + 3][bn] = bv.w;
        }
        __syncthreads();
#pragma unroll
        for (int k = 0; k < 16; k++) {
            float4 aA = *(const float4*)&As[k][ty * 8];
            float4 aB = *(const float4*)&As[k][ty * 8 + 4];
            ull b01 = *(const ull*)&Bs[k][tx * 4];
            ull b23 = *(const ull*)&Bs[k][tx * 4 + 2];
            ull ap;
            ap = pack2(aA.x, aA.x); ffma2(acc[0][0], ap, b01); ffma2(acc[0][1], ap, b23);
            ap = pack2(aA.y, aA.y); ffma2(acc[1][0], ap, b01); ffma2(acc[1][1], ap, b23);
            ap = pack2(aA.z, aA.z); ffma2(acc[2][0], ap, b01); ffma2(acc[2][1], ap, b23);
            ap = pack2(aA.w, aA.w); ffma2(acc[3][0], ap, b01); ffma2(acc[3][1], ap, b23);
            ap = pack2(aB.x, aB.x); ffma2(acc[4][0], ap, b01); ffma2(acc[4][1], ap, b23);
            ap = pack2(aB.y, aB.y); ffma2(acc[5][0], ap, b01); ffma2(acc[5][1], ap, b23);
            ap = pack2(aB.z, aB.z); ffma2(acc[6][0], ap, b01); ffma2(acc[6][1], ap, b23);
            ap = pack2(aB.w, aB.w); ffma2(acc[7][0], ap, b01); ffma2(acc[7][1], ap, b23);
        }
        __syncthreads();
    }
#pragma unroll
    for (int i = 0; i < 8; i++) {
        int m = m0 + ty * 8 + i;
#pragma unroll
        for (int p = 0; p < 2; p++) {
            float lo, hi; unpack2(lo, hi, acc[i][p]);
            int n = n0 + tx * 4 + 2 * p;
            if (!NGUARD || n < N) {
                float v = lo; if (BIAS) v += bias[n];
                C[(size_t)m * N + n] = v;
            }
            if (!NGUARD || n + 1 < N) {
                float v = hi; if (BIAS) v += bias[n + 1];
                C[(size_t)m * N + n + 1] = v;
            }
        }
    }
}

// fused 4-way projection GEMM: z selects (A, B, bias, C)
__global__ void __launch_bounds__(256) gemm_fused(const float* __restrict__ Q,
                                                  const float* __restrict__ Kin,
                                                  const float* __restrict__ V,
                                                  const float* __restrict__ Wq,
                                                  const float* __restrict__ Wk,
                                                  const float* __restrict__ Wv,
                                                  const float* __restrict__ coW,
                                                  const float* __restrict__ cob,
                                                  float* __restrict__ mq,
                                                  float* __restrict__ mk,
                                                  float* __restrict__ mv,
                                                  float* __restrict__ co)
{
    int m0 = blockIdx.x * 128, n0 = blockIdx.y * 64;
    switch (blockIdx.z) {
    case 0: gemm_core<false,false,false,false>(Q,   nullptr, Wq,  nullptr, mq, AHC, HIDC, m0, n0, 0, HIDC); break;
    case 1: gemm_core<false,false,false,false>(Kin, nullptr, Wk,  nullptr, mk, AHC, HIDC, m0, n0, 0, HIDC); break;
    case 2: gemm_core<false,false,false,false>(V,   nullptr, Wv,  nullptr, mv, AHC, HIDC, m0, n0, 0, HIDC); break;
    default:gemm_core<false,true, false,false>(V,   nullptr, coW, cob,     co, AHC, HIDC, m0, n0, 0, HIDC); break;
    }
}

// pointwise conv GEMM: mkc = dwt @ pw_w^T + sep_b
__global__ void __launch_bounds__(256) gemm_pw(const float* __restrict__ dwt,
                                               const float* __restrict__ pw,
                                               const float* __restrict__ sb,
                                               float* __restrict__ mkc)
{
    gemm_core<true, true, false, false>(dwt, nullptr, pw, sb, mkc,
                                        AHC, HIDC, blockIdx.x * 128, blockIdx.y * 64, 0, HIDC);
}

// ck logits GEMM, split-K x CKZ
__global__ void __launch_bounds__(256) gemm_ck(const float* __restrict__ mkc,
                                               const float* __restrict__ mq,
                                               const float* __restrict__ ckW,
                                               const float* __restrict__ ckb,
                                               float* __restrict__ ckp)
{
    int z = blockIdx.z;
    const int KS_ = AHC / CKZ;   // 64
    float* Cz = ckp + (size_t)z * (BB * SS * CKN);
    if (z == 0)
        gemm_core<false, true,  true, true>(mkc, mq, ckW, ckb, Cz,
                                            CKN, AHC, blockIdx.x * 128, 0, 0, KS_);
    else
        gemm_core<false, false, true, true>(mkc, mq, ckW, nullptr, Cz,
                                            CKN, AHC, blockIdx.x * 128, 0, z * KS_, z * KS_ + KS_);
}

// ck: sum CKZ partials, softmax over KS=9, write g_ck
__global__ void __launch_bounds__(256) cksm_kernel()
{
    int row = blockIdx.x * 256 + threadIdx.x;     // BB*SS*HH rows
    if (row >= BB * SS * HH) return;
    const size_t R = (size_t)BB * SS * CKN;
    const float* p0 = g_ckp + (size_t)row * KSC;
    float v[KSC];
    float m = -3e38f;
#pragma unroll
    for (int k = 0; k < KSC; k++) {
        float s = 0.f;
#pragma unroll
        for (int z = 0; z < CKZ; z++) s += p0[z * R + k];
        v[k] = s;
        m = fmaxf(m, s);
    }
    float sum = 0.f;
#pragma unroll
    for (int k = 0; k < KSC; k++) { v[k] = expf(v[k] - m); sum += v[k]; }
    float invs = 1.f / sum;
    float* o = g_ck + (size_t)row * KSC;
#pragma unroll
    for (int k = 0; k < KSC; k++) o[k] = v[k] * invs;
}

// ---------------- depthwise conv over sequence (kernel 9, pad 4) ----------------
__global__ void __launch_bounds__(256) dw_kernel(const float* __restrict__ Kin,
                                                 const float* __restrict__ dw_w)
{
    int bs = blockIdx.x;              // b*S + s
    int b = bs >> 10, s = bs & 1023;
    for (int c = threadIdx.x; c < HIDC; c += 256) {
        float acc = 0.f;
#pragma unroll
        for (int k = 0; k < KSC; k++) {
            int sr = s + k - PADC;
            if (sr >= 0 && sr < SS)
                acc += Kin[(size_t)(b * SS + sr) * HIDC + c] * dw_w[c * KSC + k];
        }
        g_dwt[(size_t)bs * HIDC + c] = acc;
    }
}

// ---------------- conv_out: sliding-window gather of co weighted by ck ----------------
__global__ void __launch_bounds__(128) conv_out_kernel(float* __restrict__ out)
{
    int bs = blockIdx.x;
    int b = bs >> 10, s = bs & 1023;
    __shared__ float cks[CKN];
    if (threadIdx.x < CKN) cks[threadIdx.x] = g_ck[(size_t)bs * CKN + threadIdx.x];
    __syncthreads();
    for (int a = threadIdx.x; a < AHC; a += 128) {
        int h = a >> 6;
        float acc = 0.f;
#pragma unroll
        for (int k = 0; k < KSC; k++) {
            int sr = s + k - PADC;
            if (sr >= 0 && sr < SS)
                acc += g_co[(size_t)(b * SS + sr) * AHC + a] * cks[h * KSC + k];
        }
        out[(size_t)bs * OW + AHC + a] = acc;
    }
}

// ---------------- td softmax (independent of head and query row) ----------------
__global__ void __launch_bounds__(256) tdsm_kernel(const float* __restrict__ td,
                                                   const int* __restrict__ mask)
{
    __shared__ float red[8];
    __shared__ float bc;
    int b = blockIdx.x, tid = threadIdx.x;
    int wid = tid >> 5, ln = tid & 31;

    float ss = 0.f;
    for (int j = tid; j < SS; j += 256) { float v = td[b * SS + j]; ss += v * v; }
#pragma unroll
    for (int o = 16; o; o >>= 1) ss += __shfl_xor_sync(0xffffffffu, ss, o);
    if (ln == 0) red[wid] = ss;
    __syncthreads();
    if (tid == 0) {
        float t = 0.f;
        for (int k = 0; k < 8; k++) t += red[k];
        bc = 1.f / fmaxf(sqrtf(t), 1e-12f);
    }
    __syncthreads();
    float inv = bc;

    float m = -1e4f;
    for (int j = tid; j < SS; j += 256)
        if (mask[b * SS + j]) m = fmaxf(m, td[b * SS + j] * inv);
#pragma unroll
    for (int o = 16; o; o >>= 1) m = fmaxf(m, __shfl_xor_sync(0xffffffffu, m, o));
    if (ln == 0) red[wid] = m;
    __syncthreads();
    if (tid == 0) {
        float t = -1e4f;
        for (int k = 0; k < 8; k++) t = fmaxf(t, red[k]);
        bc = t;
    }
    __syncthreads();
    float mm = bc;
    __syncthreads();

    float den = 0.f;
    for (int j = tid; j < SS; j += 256)
        if (mask[b * SS + j]) den += expf(td[b * SS + j] * inv - mm);
#pragma unroll
    for (int o = 16; o; o >>= 1) den += __shfl_xor_sync(0xffffffffu, den, o);
    if (ln == 0) red[wid] = den;
    __syncthreads();
    if (tid == 0) {
        float t = 0.f;
        for (int k = 0; k < 8; k++) t += red[k];
        bc = 1.f / t;
    }
    __syncthreads();
    float invden = bc;

    for (int j = tid; j < SS; j += 256) {
        float v = mask[b * SS + j] ? expf(td[b * SS + j] * inv - mm) * invden : 0.f;
        g_tdsm[b * SS + j] = v;
    }
}

// ---------------- attention with distance decay ----------------
// grid (S/16, H, B); 8 warps x 2 query rows each; 2 blocks/SM.
// K/V in 128x66 smem. Probs stored PAIRED: scp[sidx*2+rr] so PV fetches both
// rows with one uniform LDS.64. Mask as bitmask; tds bit-transposed so the
// softmax passes are conflict-free. Score passes are register-resident.
__global__ void __launch_bounds__(ATHR, 2) attn_kernel(const int* __restrict__ mask,
                                                       const float* __restrict__ gammas,
                                                       float* __restrict__ out)
{
    extern __shared__ float sm[];
    float* kt   = sm;                        // 128*66 = 8448
    float* scp  = kt + 128 * 66;             // 8 warps * 2112 = 16896
    float* qs   = scp + 8 * 2112;            // 16*64 = 1024
    float* tdsT = qs + TIQ * 64;             // 1024 (bit-transposed)
    unsigned* mbits = (unsigned*)(tdsT + 1024);  // 32 words

    const int tid  = threadIdx.x;
    const int w    = tid >> 5, lane = tid & 31;
    const int i0   = blockIdx.x * TIQ;
    const int h    = blockIdx.y;
    const int b    = blockIdx.z;
    const int r0   = w * RPW;

    // mask bits via ballot (tid covers contiguous 32-j groups per warp)
    for (int base = tid; base < SS; base += ATHR) {
        int mv = mask[b * SS + base];
        unsigned bal = __ballot_sync(0xffffffffu, mv != 0);
        if (lane == 0) mbits[base >> 5] = bal;
    }
    // tds bit-transposed: tdsT[(j&31)<<5 | j>>5] = tdsm[j]
    for (int j = tid; j < SS; j += ATHR)
        tdsT[((j & 31) << 5) | (j >> 5)] = g_tdsm[b * SS + j];
    for (int idx = tid; idx < TIQ * 32; idx += ATHR) {
        int r = idx >> 5, dp = idx & 31;
        *(float2*)&qs[r * 64 + 2 * dp] =
            *(const float2*)(g_mq + (size_t)(b * SS + i0 + r) * AHC + h * DD + 2 * dp);
    }
    float gv = gammas[h];
    float gamma = -(gv > 20.f ? gv : log1pf(expf(gv)));   // -softplus

    float* scw = scp + w * 2112;

    // ---- QK: scores for 2 rows x 128 j per warp per tile ----
    for (int jt = 0; jt < 8; jt++) {
        __syncthreads();
        for (int idx = tid; idx < 4096; idx += ATHR) {
            int r = idx >> 5, dp = idx & 31;
            *(float2*)&kt[r * 66 + 2 * dp] =
                *(const float2*)(g_mk + (size_t)(b * SS + jt * 128 + r) * AHC + h * DD + 2 * dp);
        }
        __syncthreads();
        ull acc[RPW][4];
#pragma unroll
        for (int rr = 0; rr < RPW; rr++)
#pragma unroll
            for (int c = 0; c < 4; c++) acc[rr][c] = 0ull;
#pragma unroll
        for (int dp = 0; dp < 32; dp++) {
            ull k0 = *(const ull*)&kt[(lane      ) * 66 + 2 * dp];
            ull k1 = *(const ull*)&kt[(lane +  32) * 66 + 2 * dp];
            ull k2 = *(const ull*)&kt[(lane +  64) * 66 + 2 * dp];
            ull k3 = *(const ull*)&kt[(lane +  96) * 66 + 2 * dp];
#pragma unroll
            for (int rr = 0; rr < RPW; rr++) {
                ull q2 = *(const ull*)&qs[(r0 + rr) * 64 + 2 * dp];
                ffma2(acc[rr][0], q2, k0);
                ffma2(acc[rr][1], q2, k1);
                ffma2(acc[rr][2], q2, k2);
                ffma2(acc[rr][3], q2, k3);
            }
        }
#pragma unroll
        for (int rr = 0; rr < RPW; rr++) {
#pragma unroll
            for (int c = 0; c < 4; c++) {
                float lo, hi; unpack2(lo, hi, acc[rr][c]);
                int j = jt * 128 + c * 32 + lane;
                scw[(j + (j >> 5)) * 2 + rr] = (lo + hi) * 0.125f;
            }
        }
    }
    __syncwarp();

    // ---- softmax / distance-decay, register-resident; j = lane*32+c ----
    const unsigned mrow = mbits[lane];
    float invsv[RPW];
#pragma unroll
    for (int rr = 0; rr < RPW; rr++) {
        const int i = i0 + r0 + rr;
        float sv[32];
#pragma unroll
        for (int c = 0; c < 32; c++) sv[c] = scw[(lane * 33 + c) * 2 + rr];

        // pass 1: masked max
        float m1 = -3e38f;
#pragma unroll
        for (int c = 0; c < 32; c++)
            if ((mrow >> c) & 1) m1 = fmaxf(m1, sv[c]);
#pragma unroll
        for (int o = 16; o; o >>= 1) m1 = fmaxf(m1, __shfl_xor_sync(0xffffffffu, m1, o));

        // pass 2: p ~ exp * mask, inclusive cumsum
        float cuml[32];
        float run = 0.f;
#pragma unroll
        for (int c = 0; c < 32; c++) {
            float p = ((mrow >> c) & 1) ? expf(sv[c] - m1) : 0.f;
            run += p;
            cuml[c] = run;
        }
        float v = run;
#pragma unroll
        for (int o = 1; o < 32; o <<= 1) {
            float t = __shfl_up_sync(0xffffffffu, v, o);
            if (lane >= o) v += t;
        }
        float total = __shfl_sync(0xffffffffu, v, 31);
        float off = v - run;
        float invtot = 1.f / fmaxf(total, 1e-30f);

        // pass 3: total_effect, modified scores, max (tdsT conflict-free)
        float m2 = -3e38f;
#pragma unroll
        for (int c = 0; c < 32; c++) {
            int j = lane * 32 + c;
            float s2;
            if ((mrow >> c) & 1) {
                float cum = cuml[c] + off;
                float pos = fabsf((float)(j - i));
                float rem = (total - cum) * invtot;
                float ds = sqrtf(fmaxf(rem * pos, 0.f));
                float te = expf(gamma * ds);
                te = fminf(fmaxf(te, 1e-5f), 1e5f);
                if (j < i) te -= tdsT[(c << 5) | lane];
                s2 = sv[c] * te;
            } else {
                s2 = -1e8f;
            }
            sv[c] = s2;
            m2 = fmaxf(m2, s2);
        }
#pragma unroll
        for (int o = 16; o; o >>= 1) m2 = fmaxf(m2, __shfl_xor_sync(0xffffffffu, m2, o));

        // pass 4: exp + sum, store paired
        float sum2 = 0.f;
#pragma unroll
        for (int c = 0; c < 32; c++) {
            float e = expf(sv[c] - m2);
            scw[(lane * 33 + c) * 2 + rr] = e;
            sum2 += e;
        }
#pragma unroll
        for (int o = 16; o; o >>= 1) sum2 += __shfl_xor_sync(0xffffffffu, sum2, o);
        invsv[rr] = 1.f / sum2;
    }

    // ---- PV: lane owns d-pair; both rows' probs via one uniform LDS.64 ----
    ull acc0 = 0ull, acc1 = 0ull;
    for (int jt = 0; jt < 8; jt++) {
        __syncthreads();
        for (int idx = tid; idx < 4096; idx += ATHR) {
            int r = idx >> 5, dp = idx & 31;
            *(float2*)&kt[r * 66 + 2 * dp] =
                *(const float2*)(g_mv + (size_t)(b * SS + jt * 128 + r) * AHC + h * DD + 2 * dp);
        }
        __syncthreads();
        int jb = jt * 128;
#pragma unroll 8
        for (int jl = 0; jl < 128; jl++) {
            int j = jb + jl;
            ull pr2 = *(const ull*)&scw[(j + (j >> 5)) * 2];
            float p0, p1; unpack2(p0, p1, pr2);
            ull kv = *(const ull*)&kt[jl * 66 + 2 * lane];
            ffma2(acc0, pack2(p0, p0), kv);
            ffma2(acc1, pack2(p1, p1), kv);
        }
    }
    {
        float lo, hi; unpack2(lo, hi, acc0);
        size_t ob = (size_t)(b * SS + i0 + r0) * OW + h * DD;
        *(float2*)(out + ob + 2 * lane) = make_float2(lo * invsv[0], hi * invsv[0]);
        unpack2(lo, hi, acc1);
        ob += OW;
        *(float2*)(out + ob + 2 * lane) = make_float2(lo * invsv[1], hi * invsv[1]);
    }
}

// ---------------- launch ----------------
extern "C" void kernel_launch(void* const* d_in, const int* in_sizes, int n_in,
                              void* d_out, int out_size)
{
    const float* Q      = (const float*)d_in[0];
    const float* Kin    = (const float*)d_in[1];
    const float* V      = (const float*)d_in[2];
    const float* td     = (const float*)d_in[3];
    const int*   mask   = (const int*)  d_in[4];
    const float* Wq     = (const float*)d_in[5];
    const float* Wk     = (const float*)d_in[6];
    const float* Wv     = (const float*)d_in[7];
    const float* dw_w   = (const float*)d_in[8];
    const float* pw_w   = (const float*)d_in[9];
    const float* sep_b  = (const float*)d_in[10];
    const float* ck_W   = (const float*)d_in[11];
    const float* ck_b   = (const float*)d_in[12];
    const float* co_W   = (const float*)d_in[13];
    const float* co_b   = (const float*)d_in[14];
    const float* gammas = (const float*)d_in[15];
    float* out = (float*)d_out;

    float *p_mq, *p_mk, *p_mv, *p_co, *p_mkc, *p_dwt, *p_ckp;
    cudaGetSymbolAddress((void**)&p_mq,  g_mq);
    cudaGetSymbolAddress((void**)&p_mk,  g_mk);
    cudaGetSymbolAddress((void**)&p_mv,  g_mv);
    cudaGetSymbolAddress((void**)&p_co,  g_co);
    cudaGetSymbolAddress((void**)&p_mkc, g_mkc);
    cudaGetSymbolAddress((void**)&p_dwt, g_dwt);
    cudaGetSymbolAddress((void**)&p_ckp, g_ckp);

    const int M = BB * SS;

    // launch order arranged so attn_kernel is the 4th launch (ncu captures #4)
    tdsm_kernel<<<BB, 256>>>(td, mask);                                             // 1
    gemm_fused<<<dim3(M / 128, AHC / 64, 4), 256>>>(Q, Kin, V, Wq, Wk, Wv,          // 2
                                                    co_W, co_b, p_mq, p_mk, p_mv, p_co);
    dw_kernel<<<BB * SS, 256>>>(Kin, dw_w);                                         // 3

    int smem = (128 * 66 + 8 * 2112 + TIQ * 64 + 1024 + 32) * (int)sizeof(float);
    cudaFuncSetAttribute(attn_kernel, cudaFuncAttributeMaxDynamicSharedMemorySize, smem);
    attn_kernel<<<dim3(SS / TIQ, HH, BB), ATHR, smem>>>(mask, gammas, out);         // 4

    gemm_pw<<<dim3(M / 128, AHC / 64), 256>>>(p_dwt, pw_w, sep_b, p_mkc);           // 5
    gemm_ck<<<dim3(M / 128, 1, CKZ), 256>>>(p_mkc, p_mq, ck_W, ck_b, p_ckp);        // 6
    cksm_kernel<<<(BB * SS * HH + 255) / 256, 256>>>();                             // 7
    conv_out_kernel<<<BB * SS, 128>>>(out);                                         // 8
}